// round 15
// baseline (speedup 1.0000x reference)
#include <cuda_runtime.h>
#include <cuda_fp16.h>
#include <math.h>
#include <stdint.h>

#define B_  8
#define S_  4096
#define T_  77
#define TP_ 80
#define C_  1280
#define CE_ 2048
#define H_  20
#define D_  64
#define HD_ 1280
#define KTOK_ 12
#define KPOS_ 1229
#define SCHUNK_ (S_/128)   // 32

#define SCALE_ 0.125f
#define STRENGTH_ 0.5f
#define ALPHA_ 0.7f
#define WINJ_ 0.25f

// ---------------- scratch ----------------
__device__ __half g_x16[(size_t)B_*S_*C_];
__device__ __half g_e16[B_*T_*CE_];
__device__ __half g_wq16[C_*HD_];
__device__ __half g_wk16[CE_*HD_];
__device__ __half g_wv16[CE_*HD_];
__device__ __half g_wo16[HD_*C_];
__device__ __half g_q[(size_t)B_*S_*HD_];
__device__ __half g_k16[B_*T_*HD_];
__device__ __half g_v16[B_*T_*HD_];
__device__ __half g_v216[B_*T_*HD_];
__device__ __half g_dksel[B_*16*HD_];
__device__ int   g_tokidx[B_*16];
__device__ int   g_maskidx[B_*TP_];
__device__ float g_posp[B_*H_*S_];
__device__ float g_tokpart[B_*H_*SCHUNK_*T_];
__device__ int   g_tokmask[B_*T_];
__device__ float g_posscores[B_*S_];
__device__ int   g_posmask[B_*S_];
__device__ __half g_ctx[(size_t)B_*S_*HD_];

// ---------------- helpers ----------------
__device__ __forceinline__ void mma_f16(float* c, const uint32_t* a, const uint32_t* b) {
    asm volatile(
        "mma.sync.aligned.m16n8k16.row.col.f32.f16.f16.f32 "
        "{%0,%1,%2,%3},{%4,%5,%6,%7},{%8,%9},{%0,%1,%2,%3};"
        : "+f"(c[0]), "+f"(c[1]), "+f"(c[2]), "+f"(c[3])
        : "r"(a[0]), "r"(a[1]), "r"(a[2]), "r"(a[3]), "r"(b[0]), "r"(b[1]));
}
__device__ __forceinline__ void ldmx4(uint32_t* r, const void* p) {
    uint32_t a = (uint32_t)__cvta_generic_to_shared(p);
    asm volatile("ldmatrix.sync.aligned.m8n8.x4.shared.b16 {%0,%1,%2,%3}, [%4];"
                 : "=r"(r[0]), "=r"(r[1]), "=r"(r[2]), "=r"(r[3]) : "r"(a));
}
__device__ __forceinline__ void ldmx4t(uint32_t* r, const void* p) {
    uint32_t a = (uint32_t)__cvta_generic_to_shared(p);
    asm volatile("ldmatrix.sync.aligned.m8n8.x4.trans.shared.b16 {%0,%1,%2,%3}, [%4];"
                 : "=r"(r[0]), "=r"(r[1]), "=r"(r[2]), "=r"(r[3]) : "r"(a));
}
__device__ __forceinline__ uint32_t pack_h2(float x, float y) {
    __half2 h = __floats2half2_rn(x, y);
    return *(uint32_t*)&h;
}
__device__ __forceinline__ void cpa16(uint32_t dst, const void* src, int sz) {
    asm volatile("cp.async.ca.shared.global [%0], [%1], 16, %2;"
                 :: "r"(dst), "l"(src), "r"(sz));
}

// ---------------- fp32 -> fp16 conversion ----------------
__global__ __launch_bounds__(256) void cvt16_k(
    const float* __restrict__ src, __half* __restrict__ dst, int n4)
{
    int i = blockIdx.x * 256 + threadIdx.x;
    if (i >= n4) return;
    float4 v = *(const float4*)(src + (size_t)i * 4);
    uint2 u; u.x = pack_h2(v.x, v.y); u.y = pack_h2(v.z, v.w);
    *(uint2*)(dst + (size_t)i * 4) = u;
}

// ====================================================================
//  pure-fp16 GEMM : 128x128x64 tiles, cp.async double-buffered
// ====================================================================
#define GA_P 72
#define GB_P 136
#define GSM_AS 0
#define GSM_BS (2 * 128 * GA_P * 2)
#define GSM_TOTAL (GSM_BS + 2 * 64 * GB_P * 2)

template<int OUT16, int EPI>
__global__ __launch_bounds__(256) void hgemm16_k(
    const __half* __restrict__ A, const __half* __restrict__ Bm, void* __restrict__ Cm,
    int M, int N, int K,
    const float* __restrict__ bias, const __half* __restrict__ resid16)
{
    extern __shared__ char gsm[];
    __half* As = (__half*)(gsm + GSM_AS);
    __half* Bs = (__half*)(gsm + GSM_BS);

    const int tid = threadIdx.x;
    const int wid = tid >> 5, lane = tid & 31;
    const int wm = wid & 1, wn = wid >> 1;
    const int bm0 = blockIdx.y * 128, bn0 = blockIdx.x * 128;

    float acc[4][4][4];
#pragma unroll
    for (int i = 0; i < 4; i++)
#pragma unroll
        for (int j = 0; j < 4; j++)
#pragma unroll
            for (int r = 0; r < 4; r++) acc[i][j][r] = 0.f;

    const int ltile = lane >> 3, lrit = lane & 7;
    const int a_m  = wm * 64 + (ltile & 1) * 8 + lrit;
    const int a_kc = (ltile >> 1) * 8;
    const int b_k  = (ltile & 1) * 8 + lrit;
    const int b_n  = wn * 32 + (ltile >> 1) * 8;

#define G_ISSUE(k0, buf)                                                             \
    {                                                                                \
        _Pragma("unroll")                                                            \
        for (int i = 0; i < 4; i++) {                                                \
            int cid = tid + i * 256;                                                 \
            int ar = cid >> 3, ach = (cid & 7) * 8;                                  \
            cpa16((uint32_t)__cvta_generic_to_shared(                                \
                      &As[(size_t)(buf) * 128 * GA_P + ar * GA_P + ach]),            \
                  A + (size_t)(bm0 + ar) * K + (k0) + ach, (bm0 + ar < M) ? 16 : 0); \
            int bk = cid >> 4, bch = (cid & 15) * 8;                                 \
            cpa16((uint32_t)__cvta_generic_to_shared(                                \
                      &Bs[(size_t)(buf) * 64 * GB_P + bk * GB_P + bch]),             \
                  Bm + (size_t)((k0) + bk) * N + bn0 + bch, 16);                     \
        }                                                                            \
        asm volatile("cp.async.commit_group;");                                      \
    }

    G_ISSUE(0, 0);
    const int KT = K >> 6;
    int rbuf = 0;
    for (int kt = 0; kt < KT; kt++) {
        if (kt + 1 < KT) {
            G_ISSUE((kt + 1) << 6, rbuf ^ 1);
            asm volatile("cp.async.wait_group 1;");
        } else {
            asm volatile("cp.async.wait_group 0;");
        }
        __syncthreads();

        const __half* Ab = &As[(size_t)rbuf * 128 * GA_P];
        const __half* Bb = &Bs[(size_t)rbuf * 64 * GB_P];
#pragma unroll
        for (int kk = 0; kk < 64; kk += 16) {
            uint32_t af[4][4], bf[4][2];
#pragma unroll
            for (int mt = 0; mt < 4; mt++)
                ldmx4(af[mt], &Ab[(a_m + mt * 16) * GA_P + kk + a_kc]);
#pragma unroll
            for (int p = 0; p < 2; p++) {
                uint32_t br[4];
                ldmx4t(br, &Bb[(kk + b_k) * GB_P + b_n + p * 16]);
                bf[2 * p][0]     = br[0];
                bf[2 * p][1]     = br[1];
                bf[2 * p + 1][0] = br[2];
                bf[2 * p + 1][1] = br[3];
            }
#pragma unroll
            for (int mt = 0; mt < 4; mt++)
#pragma unroll
                for (int nt = 0; nt < 4; nt++)
                    mma_f16(acc[mt][nt], af[mt], bf[nt]);
        }
        __syncthreads();
        rbuf ^= 1;
    }
#undef G_ISSUE

    const int row0 = bm0 + wm * 64 + (lane >> 2);
    const int col0 = bn0 + wn * 32 + 2 * (lane & 3);
#pragma unroll
    for (int mt = 0; mt < 4; mt++) {
#pragma unroll
        for (int nt = 0; nt < 4; nt++) {
            int r = row0 + mt * 16;
            int c = col0 + nt * 8;
            if (OUT16) {
                if (r < M)
                    *(uint32_t*)((__half*)Cm + (size_t)r * N + c) = pack_h2(acc[mt][nt][0], acc[mt][nt][1]);
                if (r + 8 < M)
                    *(uint32_t*)((__half*)Cm + (size_t)(r + 8) * N + c) = pack_h2(acc[mt][nt][2], acc[mt][nt][3]);
            } else {
                float v0 = acc[mt][nt][0], v1 = acc[mt][nt][1];
                float v2 = acc[mt][nt][2], v3 = acc[mt][nt][3];
                if (EPI) {
                    float b0v = bias[c], b1v = bias[c + 1];
                    if (r < M) {
                        uint32_t u = *(const uint32_t*)(resid16 + (size_t)r * N + c);
                        float2 rr = __half22float2(*(__half2*)&u);
                        v0 += b0v + rr.x; v1 += b1v + rr.y;
                    }
                    if (r + 8 < M) {
                        uint32_t u = *(const uint32_t*)(resid16 + (size_t)(r + 8) * N + c);
                        float2 rr = __half22float2(*(__half2*)&u);
                        v2 += b0v + rr.x; v3 += b1v + rr.y;
                    }
                }
                if (r < M) { float2 o; o.x = v0; o.y = v1; *(float2*)((float*)Cm + (size_t)r * N + c) = o; }
                if (r + 8 < M) { float2 o; o.x = v2; o.y = v3; *(float2*)((float*)Cm + (size_t)(r + 8) * N + c) = o; }
            }
        }
    }
}

// ====================================================================
//  attention pass 1
// ====================================================================
#define QP_  72
#define KP2_ 88

__global__ __launch_bounds__(256) void attn1_k(
    const __half* __restrict__ q, const __half* __restrict__ kk,
    float* __restrict__ tokpart)
{
    __shared__ __half Qs[128 * QP_];
    __shared__ __half Ks[64 * KP2_];
    __shared__ float tpw[8][TP_];

    const int b = blockIdx.z, h = blockIdx.y;
    const int tid = threadIdx.x;
    const int wid = tid >> 5, lane = tid & 31;
    const int bm0 = blockIdx.x * 128;

#pragma unroll
    for (int i = 0; i < 4; i++) {
        int f = tid + i * 256;
        int row = f >> 3, c8 = (f & 7) * 8;
        uint4 v = *(const uint4*)(q + ((size_t)(b * S_) + bm0 + row) * HD_ + h * D_ + c8);
        *(uint4*)&Qs[row * QP_ + c8] = v;
    }
    for (int f = tid; f < 64 * KP2_ / 2; f += 256) ((uint32_t*)Ks)[f] = 0;
    __syncthreads();
    for (int f = tid; f < T_ * 16; f += 256) {
        int t = f >> 4, d4 = (f & 15) * 4;
        uint2 u = *(const uint2*)(kk + ((size_t)(b * T_) + t) * HD_ + h * D_ + d4);
        const __half* hp = (const __half*)&u;
        Ks[(d4 + 0) * KP2_ + t] = hp[0];
        Ks[(d4 + 1) * KP2_ + t] = hp[1];
        Ks[(d4 + 2) * KP2_ + t] = hp[2];
        Ks[(d4 + 3) * KP2_ + t] = hp[3];
    }
    __syncthreads();

    const int ltile = lane >> 3, lrit = lane & 7;
    const int a_m  = wid * 16 + (ltile & 1) * 8 + lrit;
    const int a_kc = (ltile >> 1) * 8;
    const int b_k  = (ltile & 1) * 8 + lrit;
    const int b_n  = (ltile >> 1) * 8;

    float acc[10][4];
#pragma unroll
    for (int nt = 0; nt < 10; nt++)
#pragma unroll
        for (int r = 0; r < 4; r++) acc[nt][r] = 0.f;

#pragma unroll
    for (int kkk = 0; kkk < 64; kkk += 16) {
        uint32_t af[4], bf[10][2];
        ldmx4(af, &Qs[a_m * QP_ + kkk + a_kc]);
#pragma unroll
        for (int p = 0; p < 5; p++) {
            uint32_t br[4];
            ldmx4t(br, &Ks[(kkk + b_k) * KP2_ + b_n + p * 16]);
            bf[2 * p][0]     = br[0];
            bf[2 * p][1]     = br[1];
            bf[2 * p + 1][0] = br[2];
            bf[2 * p + 1][1] = br[3];
        }
#pragma unroll
        for (int nt = 0; nt < 10; nt++)
            mma_f16(acc[nt], af, bf[nt]);
    }

    float rs_a = 0.f, rs_b = 0.f;
#pragma unroll
    for (int nt = 0; nt < 10; nt++) {
        int col = nt * 8 + 2 * (lane & 3);
        float e0 = (col     < T_) ? __expf(acc[nt][0] * SCALE_) : 0.f;
        float e1 = (col + 1 < T_) ? __expf(acc[nt][1] * SCALE_) : 0.f;
        float e2 = (col     < T_) ? __expf(acc[nt][2] * SCALE_) : 0.f;
        float e3 = (col + 1 < T_) ? __expf(acc[nt][3] * SCALE_) : 0.f;
        acc[nt][0] = e0; acc[nt][1] = e1; acc[nt][2] = e2; acc[nt][3] = e3;
        rs_a += e0 + e1;
        rs_b += e2 + e3;
    }
    rs_a += __shfl_xor_sync(0xffffffffu, rs_a, 1);
    rs_a += __shfl_xor_sync(0xffffffffu, rs_a, 2);
    rs_b += __shfl_xor_sync(0xffffffffu, rs_b, 1);
    rs_b += __shfl_xor_sync(0xffffffffu, rs_b, 2);
    float inv_a = 1.f / rs_a;
    float inv_b = 1.f / rs_b;

#pragma unroll
    for (int nt = 0; nt < 10; nt++) {
        float cs0 = acc[nt][0] * inv_a + acc[nt][2] * inv_b;
        float cs1 = acc[nt][1] * inv_a + acc[nt][3] * inv_b;
#pragma unroll
        for (int o = 4; o <= 16; o <<= 1) {
            cs0 += __shfl_xor_sync(0xffffffffu, cs0, o);
            cs1 += __shfl_xor_sync(0xffffffffu, cs1, o);
        }
        if (lane < 4) {
            int col = nt * 8 + 2 * lane;
            tpw[wid][col]     = cs0;
            tpw[wid][col + 1] = cs1;
        }
    }
    __syncthreads();
    if (tid < T_) {
        float s = 0.f;
#pragma unroll
        for (int w = 0; w < 8; w++) s += tpw[w][tid];
        int lin = (b * H_ + h) * SCHUNK_ + blockIdx.x;
        tokpart[(size_t)lin * T_ + tid] = s;
    }
}

// ---------------- fused token reduce + top-k + compact maps ----------------
// ranking is invariant to the positive 1/(H*S) scale -> reduce without it
__global__ void tok_topk_k(const float* __restrict__ tokpart, int* __restrict__ mask,
                           int* __restrict__ tokidx, int* __restrict__ maskidx)
{
    int b = blockIdx.x, tid = threadIdx.x;
    __shared__ float sc[T_];
    __shared__ int rk[T_];
    if (tid < T_) {
        float sum = 0.f;
        const float* tp = tokpart + (size_t)b * H_ * SCHUNK_ * T_ + tid;
        for (int hc = 0; hc < H_ * SCHUNK_; hc++)
            sum += tp[(size_t)hc * T_];
        sc[tid] = sum;
    }
    __syncthreads();
    if (tid < T_) {
        float v = sc[tid];
        int rank = 0;
        for (int j = 0; j < T_; j++) {
            float u = sc[j];
            rank += (int)((u > v) || (u == v && j < tid));
        }
        rk[tid] = rank;
        mask[b * T_ + tid] = (rank < KTOK_) ? 1 : 0;
    }
    __syncthreads();
    if (tid < TP_) {
        if (tid < T_) {
            int j = 0;
            for (int jj = 0; jj < tid; jj++) j += (rk[jj] < KTOK_);
            bool m = rk[tid] < KTOK_;
            maskidx[b * TP_ + tid] = m ? j : -1;
            if (m) tokidx[b * 16 + j] = tid;
        } else {
            maskidx[b * TP_ + tid] = -1;
        }
    }
}

// ---------------- compact dK ----------------
__global__ void dksel_k(const __half* __restrict__ kin, const int* __restrict__ tokidx,
                        __half* __restrict__ dksel)
{
    int idx = blockIdx.x * blockDim.x + threadIdx.x;
    if (idx >= B_ * 16 * (HD_ / 4)) return;
    int c4 = (idx % (HD_ / 4)) * 4;
    int rem = idx / (HD_ / 4);
    int j = rem % 16, b = rem / 16;
    __half* dst = dksel + ((size_t)(b * 16 + j)) * HD_ + c4;
    if (j >= KTOK_) {
        *(uint2*)dst = make_uint2(0u, 0u);
        return;
    }
    int t = tokidx[b * 16 + j];
    uint2 ub = *(const uint2*)(kin + ((size_t)(b * T_) + t) * HD_ + c4);
    const __half* hb = (const __half*)&ub;
    float kb[4] = {__half2float(hb[0]), __half2float(hb[1]), __half2float(hb[2]), __half2float(hb[3])};
    float s[4] = {0.f, 0.f, 0.f, 0.f};
#pragma unroll
    for (int bb = 0; bb < B_; bb++) {
        uint2 u = *(const uint2*)(kin + ((size_t)(bb * T_) + t) * HD_ + c4);
        const __half* hp = (const __half*)&u;
        s[0] += __half2float(hp[0]); s[1] += __half2float(hp[1]);
        s[2] += __half2float(hp[2]); s[3] += __half2float(hp[3]);
    }
    const float w = STRENGTH_ * (1.f - ALPHA_);
    const float c7 = 1.f / (float)(B_ - 1);
    uint2 u;
    u.x = pack_h2(w * ((s[0] - kb[0]) * c7 - kb[0]), w * ((s[1] - kb[1]) * c7 - kb[1]));
    u.y = pack_h2(w * ((s[2] - kb[2]) * c7 - kb[2]), w * ((s[3] - kb[3]) * c7 - kb[3]));
    *(uint2*)dst = u;
}

// ---------------- pos partial reduce + top-k ----------------
__global__ void pos_reduce_k(const float* __restrict__ posp, float* __restrict__ scores)
{
    int idx = blockIdx.x * blockDim.x + threadIdx.x;
    if (idx >= B_ * S_) return;
    int b = idx / S_, s = idx % S_;
    float sum = 0.f;
#pragma unroll
    for (int h = 0; h < H_; h++) sum += posp[(size_t)(b * H_ + h) * S_ + s];
    scores[idx] = sum * (1.f / (float)H_);
}

__global__ __launch_bounds__(256) void pos_topk_k(const float* __restrict__ scores, int* __restrict__ mask)
{
    const int b = blockIdx.y;
    __shared__ float sc[S_];
    for (int i = threadIdx.x; i < S_; i += 256) sc[i] = scores[b * S_ + i];
    __syncthreads();
    const int i = blockIdx.x * 256 + threadIdx.x;
    float v = sc[i];
    int rank = 0;
    for (int j = 0; j < S_; j++) {
        float u = sc[j];
        rank += (int)((u > v) || (u == v && j < i));
    }
    mask[b * S_ + i] = (rank < KPOS_) ? 1 : 0;
}

// ---------------- V mixing ----------------
__global__ void vmix_k(const __half* __restrict__ vin, const int* __restrict__ tokmask,
                       __half* __restrict__ v2)
{
    int idx = blockIdx.x * blockDim.x + threadIdx.x;
    if (idx >= T_ * HD_) return;
    int t = idx / HD_;
    int c = idx % HD_;
    float vv[B_];
    float vsum = 0.f;
#pragma unroll
    for (int b = 0; b < B_; b++) {
        vv[b] = __half2float(vin[((size_t)(b * T_) + t) * HD_ + c]);
        vsum += vv[b];
    }
#pragma unroll
    for (int b = 0; b < B_; b++) {
        float tm = tokmask[b * T_ + t] ? STRENGTH_ : 0.f;
        float x  = vv[b];
        float mo = (vsum - x) * (1.f / (float)(B_ - 1));
        float mixed = ALPHA_ * x + (1.f - ALPHA_) * mo;
        v2[((size_t)(b * T_) + t) * HD_ + c] = __float2half_rn(x + tm * (mixed - x));
    }
}

// ====================================================================
//  attention pass 2
// ====================================================================
#define VP_  72
#define PP_  88
#define KDP_ 24
#define CRP_ 18
#define A2_QS 0
#define A2_KS (A2_QS + 128 * QP_ * 2)
#define A2_DK (A2_KS + 64 * KP2_ * 2)
#define A2_VS (A2_DK + 64 * KDP_ * 2)
#define A2_PS (A2_VS + TP_ * VP_ * 2)
#define A2_MS (A2_PS + 128 * PP_ * 2)
#define A2_MI (A2_MS + TP_ * 4)
#define A2_CR (A2_MI + TP_ * 4)
#define A2_SMEM (A2_CR + 128 * CRP_ * 4)

__global__ __launch_bounds__(256) void attn2_k(
    const __half* __restrict__ q, const __half* __restrict__ kk,
    const __half* __restrict__ dksel, const __half* __restrict__ v2,
    const int* __restrict__ tokmask, const int* __restrict__ maskidx,
    float* __restrict__ posp, __half* __restrict__ ctx)
{
    extern __shared__ char dsm[];
    __half* Qs = (__half*)(dsm + A2_QS);
    __half* Ks = (__half*)(dsm + A2_KS);
    __half* Dk = (__half*)(dsm + A2_DK);
    __half* Vs = (__half*)(dsm + A2_VS);
    __half* Ph = (__half*)(dsm + A2_PS);
    float*  Ms = (float*)(dsm + A2_MS);
    int*    Mi = (int*)(dsm + A2_MI);
    float*  Crs = (float*)(dsm + A2_CR);

    const int b = blockIdx.z, h = blockIdx.y;
    const int tid = threadIdx.x;
    const int wid = tid >> 5, lane = tid & 31;
    const int bm0 = blockIdx.x * 128;

#pragma unroll
    for (int i = 0; i < 4; i++) {
        int f = tid + i * 256;
        int row = f >> 3, c8 = (f & 7) * 8;
        uint4 v = *(const uint4*)(q + ((size_t)(b * S_) + bm0 + row) * HD_ + h * D_ + c8);
        *(uint4*)&Qs[row * QP_ + c8] = v;
    }
    for (int f = tid; f < 64 * KP2_ / 2; f += 256) ((uint32_t*)Ks)[f] = 0;
    for (int f = tid; f < 64 * KDP_ / 2; f += 256) ((uint32_t*)Dk)[f] = 0;
    for (int f = tid; f < TP_ * VP_ / 2; f += 256) ((uint32_t*)Vs)[f] = 0;
    if (tid < TP_) {
        Ms[tid] = (tid < T_) ? (float)tokmask[b * T_ + tid] : 0.f;
        Mi[tid] = maskidx[b * TP_ + tid];
    }
    __syncthreads();
    for (int f = tid; f < T_ * 16; f += 256) {
        int t = f >> 4, d4 = (f & 15) * 4;
        uint2 u = *(const uint2*)(kk + ((size_t)(b * T_) + t) * HD_ + h * D_ + d4);
        const __half* hp = (const __half*)&u;
        Ks[(d4 + 0) * KP2_ + t] = hp[0];
        Ks[(d4 + 1) * KP2_ + t] = hp[1];
        Ks[(d4 + 2) * KP2_ + t] = hp[2];
        Ks[(d4 + 3) * KP2_ + t] = hp[3];
    }
    for (int f = tid; f < T_ * 8; f += 256) {
        int t = f >> 3, d8 = (f & 7) * 8;
        *(uint4*)&Vs[t * VP_ + d8] =
            *(const uint4*)(v2 + ((size_t)(b * T_) + t) * HD_ + h * D_ + d8);
    }
    {
        int f = tid;
        int j = f >> 4, d4 = (f & 15) * 4;
        uint2 u = *(const uint2*)(dksel + ((size_t)(b * 16 + j)) * HD_ + h * D_ + d4);
        const __half* hp = (const __half*)&u;
        Dk[(d4 + 0) * KDP_ + j] = hp[0];
        Dk[(d4 + 1) * KDP_ + j] = hp[1];
        Dk[(d4 + 2) * KDP_ + j] = hp[2];
        Dk[(d4 + 3) * KDP_ + j] = hp[3];
    }
    __syncthreads();

    const int ltile = lane >> 3, lrit = lane & 7;
    const int a_m  = wid * 16 + (ltile & 1) * 8 + lrit;
    const int a_kc = (ltile >> 1) * 8;
    const int b_k  = (ltile & 1) * 8 + lrit;
    const int b_n  = (ltile >> 1) * 8;
    const int r0   = wid * 16 + (lane >> 2);

    float acc[10][4];
    float accc[2][4];
#pragma unroll
    for (int nt = 0; nt < 10; nt++)
#pragma unroll
        for (int r = 0; r < 4; r++) acc[nt][r] = 0.f;
#pragma unroll
    for (int nt = 0; nt < 2; nt++)
#pragma unroll
        for (int r = 0; r < 4; r++) accc[nt][r] = 0.f;

#pragma unroll
    for (int kkk = 0; kkk < 64; kkk += 16) {
        uint32_t af[4], bf[10][2];
        ldmx4(af, &Qs[a_m * QP_ + kkk + a_kc]);
#pragma unroll
        for (int p = 0; p < 5; p++) {
            uint32_t br[4];
            ldmx4t(br, &Ks[(kkk + b_k) * KP2_ + b_n + p * 16]);
            bf[2 * p][0]     = br[0];
            bf[2 * p][1]     = br[1];
            bf[2 * p + 1][0] = br[2];
            bf[2 * p + 1][1] = br[3];
        }
#pragma unroll
        for (int nt = 0; nt < 10; nt++)
            mma_f16(acc[nt], af, bf[nt]);
        {
            uint32_t br[4];
            ldmx4t(br, &Dk[(kkk + b_k) * KDP_ + b_n]);
            uint32_t c0[2] = {br[0], br[1]};
            uint32_t c1[2] = {br[2], br[3]};
            mma_f16(accc[0], af, c0);
            mma_f16(accc[1], af, c1);
        }
    }

#pragma unroll
    for (int nt = 0; nt < 2; nt++) {
        int ccol = nt * 8 + 2 * (lane & 3);
        Crs[r0 * CRP_ + ccol]           = accc[nt][0];
        Crs[r0 * CRP_ + ccol + 1]       = accc[nt][1];
        Crs[(r0 + 8) * CRP_ + ccol]     = accc[nt][2];
        Crs[(r0 + 8) * CRP_ + ccol + 1] = accc[nt][3];
    }
    __syncwarp();

    float rsA_a = 0.f, rsA_b = 0.f, msA_a = 0.f, msA_b = 0.f;
    float rs2_a = 0.f, rs2_b = 0.f;
#pragma unroll
    for (int nt = 0; nt < 10; nt++) {
        int col = nt * 8 + 2 * (lane & 3);
        float m0 = Ms[col], m1 = Ms[col + 1];
        int j0 = Mi[col], j1 = Mi[col + 1];
        float l0 = acc[nt][0], l1 = acc[nt][1], l2 = acc[nt][2], l3 = acc[nt][3];
        float e0 = (col     < T_) ? __expf(l0 * SCALE_) : 0.f;
        float e1 = (col + 1 < T_) ? __expf(l1 * SCALE_) : 0.f;
        float e2 = (col     < T_) ? __expf(l2 * SCALE_) : 0.f;
        float e3 = (col + 1 < T_) ? __expf(l3 * SCALE_) : 0.f;
        rsA_a += e0 + e1; rsA_b += e2 + e3;
        msA_a += e0 * m0 + e1 * m1;
        msA_b += e2 * m0 + e3 * m1;
        float f0 = (j0 >= 0) ? __expf((l0 + Crs[r0 * CRP_ + j0]) * SCALE_) : e0;
        float f1 = (j1 >= 0) ? __expf((l1 + Crs[r0 * CRP_ + j1]) * SCALE_) : e1;
        float f2 = (j0 >= 0) ? __expf((l2 + Crs[(r0 + 8) * CRP_ + j0]) * SCALE_) : e2;
        float f3 = (j1 >= 0) ? __expf((l3 + Crs[(r0 + 8) * CRP_ + j1]) * SCALE_) : e3;
        rs2_a += f0 + f1; rs2_b += f2 + f3;
        acc[nt][0] = f0; acc[nt][1] = f1; acc[nt][2] = f2; acc[nt][3] = f3;
    }
    rsA_a += __shfl_xor_sync(0xffffffffu, rsA_a, 1);
    rsA_a += __shfl_xor_sync(0xffffffffu, rsA_a, 2);
    rsA_b += __shfl_xor_sync(0xffffffffu, rsA_b, 1);
    rsA_b += __shfl_xor_sync(0xffffffffu, rsA_b, 2);
    msA_a += __shfl_xor_sync(0xffffffffu, msA_a, 1);
    msA_a += __shfl_xor_sync(0xffffffffu, msA_a, 2);
    msA_b += __shfl_xor_sync(0xffffffffu, msA_b, 1);
    msA_b += __shfl_xor_sync(0xffffffffu, msA_b, 2);
    rs2_a += __shfl_xor_sync(0xffffffffu, rs2_a, 1);
    rs2_a += __shfl_xor_sync(0xffffffffu, rs2_a, 2);
    rs2_b += __shfl_xor_sync(0xffffffffu, rs2_b, 1);
    rs2_b += __shfl_xor_sync(0xffffffffu, rs2_b, 2);

    if ((lane & 3) == 0) {
        const size_t pb2 = (size_t)(b * H_ + h) * S_ + bm0;
        posp[pb2 + r0]     = msA_a / rsA_a;
        posp[pb2 + r0 + 8] = msA_b / rsA_b;
    }

    float inv_a = 1.f / rs2_a;
    float inv_b = 1.f / rs2_b;
#pragma unroll
    for (int nt = 0; nt < 10; nt++) {
        int col = nt * 8 + 2 * (lane & 3);
        *(uint32_t*)&Ph[r0 * PP_ + col] =
            pack_h2(acc[nt][0] * inv_a, acc[nt][1] * inv_a);
        *(uint32_t*)&Ph[(r0 + 8) * PP_ + col] =
            pack_h2(acc[nt][2] * inv_b, acc[nt][3] * inv_b);
    }
    __syncthreads();

    float acc2[8][4];
#pragma unroll
    for (int nt = 0; nt < 8; nt++)
#pragma unroll
        for (int r = 0; r < 4; r++) acc2[nt][r] = 0.f;

#pragma unroll
    for (int kkk = 0; kkk < TP_; kkk += 16) {
        uint32_t af[4], bf[8][2];
        ldmx4(af, &Ph[a_m * PP_ + kkk + a_kc]);
#pragma unroll
        for (int p = 0; p < 4; p++) {
            uint32_t br[4];
            ldmx4t(br, &Vs[(kkk + b_k) * VP_ + b_n + p * 16]);
            bf[2 * p][0]     = br[0];
            bf[2 * p][1]     = br[1];
            bf[2 * p + 1][0] = br[2];
            bf[2 * p + 1][1] = br[3];
        }
#pragma unroll
        for (int nt = 0; nt < 8; nt++)
            mma_f16(acc2[nt], af, bf[nt]);
    }

#pragma unroll
    for (int nt = 0; nt < 8; nt++) {
        int col = nt * 8 + 2 * (lane & 3);
        *(uint32_t*)(ctx + ((size_t)(b * S_) + bm0 + r0) * HD_ + h * D_ + col) =
            pack_h2(acc2[nt][0], acc2[nt][1]);
        *(uint32_t*)(ctx + ((size_t)(b * S_) + bm0 + r0 + 8) * HD_ + h * D_ + col) =
            pack_h2(acc2[nt][2], acc2[nt][3]);
    }
}

// ---------------- fused batch-sum + patch injection (2 groups/thread) ----------------
#define NG8_ (S_ * HD_ / 8)
__global__ __launch_bounds__(256) void inject_fused_k(
    __half* __restrict__ ctx, const int* __restrict__ posmask)
{
    const int g = blockIdx.x * 256 + threadIdx.x;
    if (g >= NG8_ / 2) return;
#pragma unroll
    for (int half = 0; half < 2; half++) {
        const int i8 = g + half * (NG8_ / 2);
        const size_t base = (size_t)i8 * 8;
        const int s = (int)(base / HD_);

        float v[B_][8];
        float sum[8] = {0.f, 0.f, 0.f, 0.f, 0.f, 0.f, 0.f, 0.f};
#pragma unroll
        for (int b = 0; b < B_; b++) {
            uint4 u = *(const uint4*)(ctx + (size_t)b * S_ * HD_ + base);
            float2 f0 = __half22float2(*(__half2*)&u.x);
            float2 f1 = __half22float2(*(__half2*)&u.y);
            float2 f2 = __half22float2(*(__half2*)&u.z);
            float2 f3 = __half22float2(*(__half2*)&u.w);
            v[b][0] = f0.x; v[b][1] = f0.y; v[b][2] = f1.x; v[b][3] = f1.y;
            v[b][4] = f2.x; v[b][5] = f2.y; v[b][6] = f3.x; v[b][7] = f3.y;
#pragma unroll
            for (int j = 0; j < 8; j++) sum[j] += v[b][j];
        }
        const float c7 = 1.f / (float)(B_ - 1);
#pragma unroll
        for (int b = 0; b < B_; b++) {
            if (posmask[b * S_ + s]) {
                float o[8];
#pragma unroll
                for (int j = 0; j < 8; j++)
                    o[j] = v[b][j] + WINJ_ * ((sum[j] - v[b][j]) * c7 - v[b][j]);
                uint4 u;
                u.x = pack_h2(o[0], o[1]);
                u.y = pack_h2(o[2], o[3]);
                u.z = pack_h2(o[4], o[5]);
                u.w = pack_h2(o[6], o[7]);
                *(uint4*)(ctx + (size_t)b * S_ * HD_ + base) = u;
            }
        }
    }
}

// ---------------- launch ----------------
extern "C" void kernel_launch(void* const* d_in, const int* in_sizes, int n_in,
                              void* d_out, int out_size)
{
    (void)in_sizes; (void)n_in; (void)out_size;
    const float* X  = (const float*)d_in[0];
    const float* E  = (const float*)d_in[1];
    const float* Wq = (const float*)d_in[2];
    const float* Wk = (const float*)d_in[3];
    const float* Wv = (const float*)d_in[4];
    const float* Wo = (const float*)d_in[5];
    const float* bo = (const float*)d_in[6];
    float* out = (float*)d_out;

    __half *x16, *e16, *wq16, *wk16, *wv16, *wo16, *q, *k16, *v16, *v216, *dksel, *ctx;
    float *posp, *tokpart, *posscores;
    int *tokmask, *posmask, *tokidx, *maskidx;
    cudaGetSymbolAddress((void**)&x16,      g_x16);
    cudaGetSymbolAddress((void**)&e16,      g_e16);
    cudaGetSymbolAddress((void**)&wq16,     g_wq16);
    cudaGetSymbolAddress((void**)&wk16,     g_wk16);
    cudaGetSymbolAddress((void**)&wv16,     g_wv16);
    cudaGetSymbolAddress((void**)&wo16,     g_wo16);
    cudaGetSymbolAddress((void**)&q,        g_q);
    cudaGetSymbolAddress((void**)&k16,      g_k16);
    cudaGetSymbolAddress((void**)&v16,      g_v16);
    cudaGetSymbolAddress((void**)&v216,     g_v216);
    cudaGetSymbolAddress((void**)&dksel,    g_dksel);
    cudaGetSymbolAddress((void**)&tokidx,   g_tokidx);
    cudaGetSymbolAddress((void**)&maskidx,  g_maskidx);
    cudaGetSymbolAddress((void**)&posp,     g_posp);
    cudaGetSymbolAddress((void**)&tokpart,  g_tokpart);
    cudaGetSymbolAddress((void**)&tokmask,  g_tokmask);
    cudaGetSymbolAddress((void**)&posscores,g_posscores);
    cudaGetSymbolAddress((void**)&posmask,  g_posmask);
    cudaGetSymbolAddress((void**)&ctx,      g_ctx);

    cudaFuncSetAttribute(attn2_k, cudaFuncAttributeMaxDynamicSharedMemorySize, A2_SMEM);
    cudaFuncSetAttribute(hgemm16_k<1, 0>, cudaFuncAttributeMaxDynamicSharedMemorySize, GSM_TOTAL);
    cudaFuncSetAttribute(hgemm16_k<0, 1>, cudaFuncAttributeMaxDynamicSharedMemorySize, GSM_TOTAL);

    static cudaStream_t s2 = nullptr, s3 = nullptr;
    static cudaEvent_t evA = nullptr, evB = nullptr, evW = nullptr, evC2 = nullptr;
    if (s2 == nullptr) {
        cudaStreamCreateWithFlags(&s2, cudaStreamNonBlocking);
        cudaStreamCreateWithFlags(&s3, cudaStreamNonBlocking);
        cudaEventCreateWithFlags(&evA, cudaEventDisableTiming);
        cudaEventCreateWithFlags(&evB, cudaEventDisableTiming);
        cudaEventCreateWithFlags(&evW, cudaEventDisableTiming);
        cudaEventCreateWithFlags(&evC2, cudaEventDisableTiming);
    }

    const int MH = B_ * S_ / 2;            // 16384 rows (half of M)
    const int XH4 = MH * C_ / 4;           // float4 count per X half

    // fork A: side stream s2 — Wq weight cvt first, then E/W cvts + K/V projections
    cudaEventRecord(evA, 0);
    cudaStreamWaitEvent(s2, evA, 0);
    cudaStreamWaitEvent(s3, evA, 0);
    cvt16_k<<<(C_ * HD_ / 4 + 255) / 256, 256, 0, s2>>>(Wq, wq16, C_ * HD_ / 4);
    cudaEventRecord(evW, s2);
    cvt16_k<<<(B_ * T_ * CE_ / 4 + 255) / 256, 256, 0, s2>>>(E, e16, B_ * T_ * CE_ / 4);
    cvt16_k<<<(CE_ * HD_ / 4 + 255) / 256, 256, 0, s2>>>(Wk, wk16, CE_ * HD_ / 4);
    cvt16_k<<<(CE_ * HD_ / 4 + 255) / 256, 256, 0, s2>>>(Wv, wv16, CE_ * HD_ / 4);
    cvt16_k<<<(HD_ * C_ / 4 + 255) / 256, 256, 0, s2>>>(Wo, wo16, HD_ * C_ / 4);
    hgemm16_k<1, 0><<<dim3(HD_ / 128, (B_ * T_ + 127) / 128), 256, GSM_TOTAL, s2>>>(
        e16, wk16, k16, B_ * T_, HD_, CE_, nullptr, nullptr);
    hgemm16_k<1, 0><<<dim3(HD_ / 128, (B_ * T_ + 127) / 128), 256, GSM_TOTAL, s2>>>(
        e16, wv16, v16, B_ * T_, HD_, CE_, nullptr, nullptr);
    cudaEventRecord(evB, s2);

    // fork B: s3 converts X half 2 concurrent with main's half-1 cvt + Wq half-1
    cvt16_k<<<(XH4 + 255) / 256, 256, 0, s3>>>(X + (size_t)MH * C_, x16 + (size_t)MH * C_, XH4);
    cudaEventRecord(evC2, s3);

    // main: X half-1 cvt, then Wq in two M-halves
    cvt16_k<<<(XH4 + 255) / 256, 256>>>(X, x16, XH4);
    cudaStreamWaitEvent(0, evW, 0);
    hgemm16_k<1, 0><<<dim3(HD_ / 128, MH / 128), 256, GSM_TOTAL>>>(
        x16, wq16, q, MH, HD_, C_, nullptr, nullptr);
    cudaStreamWaitEvent(0, evC2, 0);
    hgemm16_k<1, 0><<<dim3(HD_ / 128, MH / 128), 256, GSM_TOTAL>>>(
        x16 + (size_t)MH * C_, wq16, q + (size_t)MH * HD_, MH, HD_, C_, nullptr, nullptr);
    cudaStreamWaitEvent(0, evB, 0);

    // attn pass 1 -> fused token reduce/top-k/compact maps
    attn1_k<<<dim3(SCHUNK_, H_, B_), 256>>>(q, k16, tokpart);
    tok_topk_k<<<B_, 128>>>(tokpart, tokmask, tokidx, maskidx);

    // V mixing + compact dK
    vmix_k<<<(T_ * HD_ + 255) / 256, 256>>>(v16, tokmask, v216);
    dksel_k<<<(B_ * 16 * (HD_ / 4) + 255) / 256, 256>>>(k16, tokidx, dksel);

    // attn pass 2 -> pos partials + fp16 ctx
    attn2_k<<<dim3(SCHUNK_, H_, B_), 256, A2_SMEM>>>(q, k16, dksel, v216, tokmask, maskidx, posp, ctx);

    // pos mask
    pos_reduce_k<<<(B_ * S_ + 255) / 256, 256>>>(posp, posscores);
    pos_topk_k<<<dim3(S_ / 256, B_), 256>>>(posscores, posmask);

    // injection (2 groups per thread)
    inject_fused_k<<<(NG8_ / 2 + 255) / 256, 256>>>(ctx, posmask);

    // output projection + bias + fp16 residual
    hgemm16_k<0, 1><<<dim3(HD_ / 128, (B_ * S_) / 128), 256, GSM_TOTAL>>>(
        ctx, wo16, out, B_ * S_, HD_, C_, bo, x16);
}

// round 16
// speedup vs baseline: 1.0008x; 1.0008x over previous
#include <cuda_runtime.h>
#include <cuda_fp16.h>
#include <math.h>
#include <stdint.h>

#define B_  8
#define S_  4096
#define T_  77
#define TP_ 80
#define C_  1280
#define CE_ 2048
#define H_  20
#define D_  64
#define HD_ 1280
#define KTOK_ 12
#define KPOS_ 1229
#define SCHUNK_ (S_/128)   // 32

#define SCALE_ 0.125f
#define STRENGTH_ 0.5f
#define ALPHA_ 0.7f
#define WINJ_ 0.25f

// ---------------- scratch ----------------
__device__ __half g_x16[(size_t)B_*S_*C_];
__device__ __half g_e16[B_*T_*CE_];
__device__ __half g_wq16[C_*HD_];
__device__ __half g_wk16[CE_*HD_];
__device__ __half g_wv16[CE_*HD_];
__device__ __half g_wo16[HD_*C_];
__device__ __half g_q[(size_t)B_*S_*HD_];
__device__ __half g_k16[B_*T_*HD_];
__device__ __half g_v16[B_*T_*HD_];
__device__ __half g_v216[B_*T_*HD_];
__device__ __half g_dksel[B_*16*HD_];
__device__ int   g_tokidx[B_*16];
__device__ int   g_maskidx[B_*TP_];
__device__ float g_posp[B_*H_*S_];
__device__ float g_tokpart[B_*H_*SCHUNK_*T_];
__device__ int   g_tokmask[B_*T_];
__device__ float g_posscores[B_*S_];
__device__ int   g_posmask[B_*S_];
__device__ __half g_ctx[(size_t)B_*S_*HD_];

// ---------------- helpers ----------------
__device__ __forceinline__ void mma_f16(float* c, const uint32_t* a, const uint32_t* b) {
    asm volatile(
        "mma.sync.aligned.m16n8k16.row.col.f32.f16.f16.f32 "
        "{%0,%1,%2,%3},{%4,%5,%6,%7},{%8,%9},{%0,%1,%2,%3};"
        : "+f"(c[0]), "+f"(c[1]), "+f"(c[2]), "+f"(c[3])
        : "r"(a[0]), "r"(a[1]), "r"(a[2]), "r"(a[3]), "r"(b[0]), "r"(b[1]));
}
__device__ __forceinline__ void ldmx4(uint32_t* r, const void* p) {
    uint32_t a = (uint32_t)__cvta_generic_to_shared(p);
    asm volatile("ldmatrix.sync.aligned.m8n8.x4.shared.b16 {%0,%1,%2,%3}, [%4];"
                 : "=r"(r[0]), "=r"(r[1]), "=r"(r[2]), "=r"(r[3]) : "r"(a));
}
__device__ __forceinline__ void ldmx4t(uint32_t* r, const void* p) {
    uint32_t a = (uint32_t)__cvta_generic_to_shared(p);
    asm volatile("ldmatrix.sync.aligned.m8n8.x4.trans.shared.b16 {%0,%1,%2,%3}, [%4];"
                 : "=r"(r[0]), "=r"(r[1]), "=r"(r[2]), "=r"(r[3]) : "r"(a));
}
__device__ __forceinline__ uint32_t pack_h2(float x, float y) {
    __half2 h = __floats2half2_rn(x, y);
    return *(uint32_t*)&h;
}
__device__ __forceinline__ void cpa16(uint32_t dst, const void* src, int sz) {
    asm volatile("cp.async.ca.shared.global [%0], [%1], 16, %2;"
                 :: "r"(dst), "l"(src), "r"(sz));
}

// ---------------- fp32 -> fp16 conversion ----------------
__global__ __launch_bounds__(256) void cvt16_k(
    const float* __restrict__ src, __half* __restrict__ dst, int n4)
{
    int i = blockIdx.x * 256 + threadIdx.x;
    if (i >= n4) return;
    float4 v = *(const float4*)(src + (size_t)i * 4);
    uint2 u; u.x = pack_h2(v.x, v.y); u.y = pack_h2(v.z, v.w);
    *(uint2*)(dst + (size_t)i * 4) = u;
}

// ====================================================================
//  pure-fp16 GEMM : 128x128x64 tiles, cp.async double-buffered
// ====================================================================
#define GA_P 72
#define GB_P 136
#define GSM_AS 0
#define GSM_BS (2 * 128 * GA_P * 2)
#define GSM_TOTAL (GSM_BS + 2 * 64 * GB_P * 2)

template<int OUT16, int EPI>
__global__ __launch_bounds__(256) void hgemm16_k(
    const __half* __restrict__ A, const __half* __restrict__ Bm, void* __restrict__ Cm,
    int M, int N, int K,
    const float* __restrict__ bias, const __half* __restrict__ resid16)
{
    extern __shared__ char gsm[];
    __half* As = (__half*)(gsm + GSM_AS);
    __half* Bs = (__half*)(gsm + GSM_BS);

    const int tid = threadIdx.x;
    const int wid = tid >> 5, lane = tid & 31;
    const int wm = wid & 1, wn = wid >> 1;
    const int bm0 = blockIdx.y * 128, bn0 = blockIdx.x * 128;

    float acc[4][4][4];
#pragma unroll
    for (int i = 0; i < 4; i++)
#pragma unroll
        for (int j = 0; j < 4; j++)
#pragma unroll
            for (int r = 0; r < 4; r++) acc[i][j][r] = 0.f;

    const int ltile = lane >> 3, lrit = lane & 7;
    const int a_m  = wm * 64 + (ltile & 1) * 8 + lrit;
    const int a_kc = (ltile >> 1) * 8;
    const int b_k  = (ltile & 1) * 8 + lrit;
    const int b_n  = wn * 32 + (ltile >> 1) * 8;

#define G_ISSUE(k0, buf)                                                             \
    {                                                                                \
        _Pragma("unroll")                                                            \
        for (int i = 0; i < 4; i++) {                                                \
            int cid = tid + i * 256;                                                 \
            int ar = cid >> 3, ach = (cid & 7) * 8;                                  \
            cpa16((uint32_t)__cvta_generic_to_shared(                                \
                      &As[(size_t)(buf) * 128 * GA_P + ar * GA_P + ach]),            \
                  A + (size_t)(bm0 + ar) * K + (k0) + ach, (bm0 + ar < M) ? 16 : 0); \
            int bk = cid >> 4, bch = (cid & 15) * 8;                                 \
            cpa16((uint32_t)__cvta_generic_to_shared(                                \
                      &Bs[(size_t)(buf) * 64 * GB_P + bk * GB_P + bch]),             \
                  Bm + (size_t)((k0) + bk) * N + bn0 + bch, 16);                     \
        }                                                                            \
        asm volatile("cp.async.commit_group;");                                      \
    }

    G_ISSUE(0, 0);
    const int KT = K >> 6;
    int rbuf = 0;
    for (int kt = 0; kt < KT; kt++) {
        if (kt + 1 < KT) {
            G_ISSUE((kt + 1) << 6, rbuf ^ 1);
            asm volatile("cp.async.wait_group 1;");
        } else {
            asm volatile("cp.async.wait_group 0;");
        }
        __syncthreads();

        const __half* Ab = &As[(size_t)rbuf * 128 * GA_P];
        const __half* Bb = &Bs[(size_t)rbuf * 64 * GB_P];
#pragma unroll
        for (int kk = 0; kk < 64; kk += 16) {
            uint32_t af[4][4], bf[4][2];
#pragma unroll
            for (int mt = 0; mt < 4; mt++)
                ldmx4(af[mt], &Ab[(a_m + mt * 16) * GA_P + kk + a_kc]);
#pragma unroll
            for (int p = 0; p < 2; p++) {
                uint32_t br[4];
                ldmx4t(br, &Bb[(kk + b_k) * GB_P + b_n + p * 16]);
                bf[2 * p][0]     = br[0];
                bf[2 * p][1]     = br[1];
                bf[2 * p + 1][0] = br[2];
                bf[2 * p + 1][1] = br[3];
            }
#pragma unroll
            for (int mt = 0; mt < 4; mt++)
#pragma unroll
                for (int nt = 0; nt < 4; nt++)
                    mma_f16(acc[mt][nt], af[mt], bf[nt]);
        }
        __syncthreads();
        rbuf ^= 1;
    }
#undef G_ISSUE

    const int row0 = bm0 + wm * 64 + (lane >> 2);
    const int col0 = bn0 + wn * 32 + 2 * (lane & 3);
#pragma unroll
    for (int mt = 0; mt < 4; mt++) {
#pragma unroll
        for (int nt = 0; nt < 4; nt++) {
            int r = row0 + mt * 16;
            int c = col0 + nt * 8;
            if (OUT16) {
                if (r < M)
                    *(uint32_t*)((__half*)Cm + (size_t)r * N + c) = pack_h2(acc[mt][nt][0], acc[mt][nt][1]);
                if (r + 8 < M)
                    *(uint32_t*)((__half*)Cm + (size_t)(r + 8) * N + c) = pack_h2(acc[mt][nt][2], acc[mt][nt][3]);
            } else {
                float v0 = acc[mt][nt][0], v1 = acc[mt][nt][1];
                float v2 = acc[mt][nt][2], v3 = acc[mt][nt][3];
                if (EPI) {
                    float b0v = bias[c], b1v = bias[c + 1];
                    if (r < M) {
                        uint32_t u = *(const uint32_t*)(resid16 + (size_t)r * N + c);
                        float2 rr = __half22float2(*(__half2*)&u);
                        v0 += b0v + rr.x; v1 += b1v + rr.y;
                    }
                    if (r + 8 < M) {
                        uint32_t u = *(const uint32_t*)(resid16 + (size_t)(r + 8) * N + c);
                        float2 rr = __half22float2(*(__half2*)&u);
                        v2 += b0v + rr.x; v3 += b1v + rr.y;
                    }
                }
                if (r < M) { float2 o; o.x = v0; o.y = v1; *(float2*)((float*)Cm + (size_t)r * N + c) = o; }
                if (r + 8 < M) { float2 o; o.x = v2; o.y = v3; *(float2*)((float*)Cm + (size_t)(r + 8) * N + c) = o; }
            }
        }
    }
}

// ====================================================================
//  attention pass 1
// ====================================================================
#define QP_  72
#define KP2_ 88

__global__ __launch_bounds__(256) void attn1_k(
    const __half* __restrict__ q, const __half* __restrict__ kk,
    float* __restrict__ tokpart)
{
    __shared__ __half Qs[128 * QP_];
    __shared__ __half Ks[64 * KP2_];
    __shared__ float tpw[8][TP_];

    const int b = blockIdx.z, h = blockIdx.y;
    const int tid = threadIdx.x;
    const int wid = tid >> 5, lane = tid & 31;
    const int bm0 = blockIdx.x * 128;

#pragma unroll
    for (int i = 0; i < 4; i++) {
        int f = tid + i * 256;
        int row = f >> 3, c8 = (f & 7) * 8;
        uint4 v = *(const uint4*)(q + ((size_t)(b * S_) + bm0 + row) * HD_ + h * D_ + c8);
        *(uint4*)&Qs[row * QP_ + c8] = v;
    }
    for (int f = tid; f < 64 * KP2_ / 2; f += 256) ((uint32_t*)Ks)[f] = 0;
    __syncthreads();
    for (int f = tid; f < T_ * 16; f += 256) {
        int t = f >> 4, d4 = (f & 15) * 4;
        uint2 u = *(const uint2*)(kk + ((size_t)(b * T_) + t) * HD_ + h * D_ + d4);
        const __half* hp = (const __half*)&u;
        Ks[(d4 + 0) * KP2_ + t] = hp[0];
        Ks[(d4 + 1) * KP2_ + t] = hp[1];
        Ks[(d4 + 2) * KP2_ + t] = hp[2];
        Ks[(d4 + 3) * KP2_ + t] = hp[3];
    }
    __syncthreads();

    const int ltile = lane >> 3, lrit = lane & 7;
    const int a_m  = wid * 16 + (ltile & 1) * 8 + lrit;
    const int a_kc = (ltile >> 1) * 8;
    const int b_k  = (ltile & 1) * 8 + lrit;
    const int b_n  = (ltile >> 1) * 8;

    float acc[10][4];
#pragma unroll
    for (int nt = 0; nt < 10; nt++)
#pragma unroll
        for (int r = 0; r < 4; r++) acc[nt][r] = 0.f;

#pragma unroll
    for (int kkk = 0; kkk < 64; kkk += 16) {
        uint32_t af[4], bf[10][2];
        ldmx4(af, &Qs[a_m * QP_ + kkk + a_kc]);
#pragma unroll
        for (int p = 0; p < 5; p++) {
            uint32_t br[4];
            ldmx4t(br, &Ks[(kkk + b_k) * KP2_ + b_n + p * 16]);
            bf[2 * p][0]     = br[0];
            bf[2 * p][1]     = br[1];
            bf[2 * p + 1][0] = br[2];
            bf[2 * p + 1][1] = br[3];
        }
#pragma unroll
        for (int nt = 0; nt < 10; nt++)
            mma_f16(acc[nt], af, bf[nt]);
    }

    float rs_a = 0.f, rs_b = 0.f;
#pragma unroll
    for (int nt = 0; nt < 10; nt++) {
        int col = nt * 8 + 2 * (lane & 3);
        float e0 = (col     < T_) ? __expf(acc[nt][0] * SCALE_) : 0.f;
        float e1 = (col + 1 < T_) ? __expf(acc[nt][1] * SCALE_) : 0.f;
        float e2 = (col     < T_) ? __expf(acc[nt][2] * SCALE_) : 0.f;
        float e3 = (col + 1 < T_) ? __expf(acc[nt][3] * SCALE_) : 0.f;
        acc[nt][0] = e0; acc[nt][1] = e1; acc[nt][2] = e2; acc[nt][3] = e3;
        rs_a += e0 + e1;
        rs_b += e2 + e3;
    }
    rs_a += __shfl_xor_sync(0xffffffffu, rs_a, 1);
    rs_a += __shfl_xor_sync(0xffffffffu, rs_a, 2);
    rs_b += __shfl_xor_sync(0xffffffffu, rs_b, 1);
    rs_b += __shfl_xor_sync(0xffffffffu, rs_b, 2);
    float inv_a = 1.f / rs_a;
    float inv_b = 1.f / rs_b;

#pragma unroll
    for (int nt = 0; nt < 10; nt++) {
        float cs0 = acc[nt][0] * inv_a + acc[nt][2] * inv_b;
        float cs1 = acc[nt][1] * inv_a + acc[nt][3] * inv_b;
#pragma unroll
        for (int o = 4; o <= 16; o <<= 1) {
            cs0 += __shfl_xor_sync(0xffffffffu, cs0, o);
            cs1 += __shfl_xor_sync(0xffffffffu, cs1, o);
        }
        if (lane < 4) {
            int col = nt * 8 + 2 * lane;
            tpw[wid][col]     = cs0;
            tpw[wid][col + 1] = cs1;
        }
    }
    __syncthreads();
    if (tid < T_) {
        float s = 0.f;
#pragma unroll
        for (int w = 0; w < 8; w++) s += tpw[w][tid];
        int lin = (b * H_ + h) * SCHUNK_ + blockIdx.x;
        tokpart[(size_t)lin * T_ + tid] = s;
    }
}

// ---------------- fused token reduce + top-k + compact maps ----------------
__global__ void tok_topk_k(const float* __restrict__ tokpart, int* __restrict__ mask,
                           int* __restrict__ tokidx, int* __restrict__ maskidx)
{
    int b = blockIdx.x, tid = threadIdx.x;
    __shared__ float sc[T_];
    __shared__ int rk[T_];
    if (tid < T_) {
        float sum = 0.f;
        const float* tp = tokpart + (size_t)b * H_ * SCHUNK_ * T_ + tid;
        for (int hc = 0; hc < H_ * SCHUNK_; hc++)
            sum += tp[(size_t)hc * T_];
        sc[tid] = sum;
    }
    __syncthreads();
    if (tid < T_) {
        float v = sc[tid];
        int rank = 0;
        for (int j = 0; j < T_; j++) {
            float u = sc[j];
            rank += (int)((u > v) || (u == v && j < tid));
        }
        rk[tid] = rank;
        mask[b * T_ + tid] = (rank < KTOK_) ? 1 : 0;
    }
    __syncthreads();
    if (tid < TP_) {
        if (tid < T_) {
            int j = 0;
            for (int jj = 0; jj < tid; jj++) j += (rk[jj] < KTOK_);
            bool m = rk[tid] < KTOK_;
            maskidx[b * TP_ + tid] = m ? j : -1;
            if (m) tokidx[b * 16 + j] = tid;
        } else {
            maskidx[b * TP_ + tid] = -1;
        }
    }
}

// ---------------- compact dK ----------------
__global__ void dksel_k(const __half* __restrict__ kin, const int* __restrict__ tokidx,
                        __half* __restrict__ dksel)
{
    int idx = blockIdx.x * blockDim.x + threadIdx.x;
    if (idx >= B_ * 16 * (HD_ / 4)) return;
    int c4 = (idx % (HD_ / 4)) * 4;
    int rem = idx / (HD_ / 4);
    int j = rem % 16, b = rem / 16;
    __half* dst = dksel + ((size_t)(b * 16 + j)) * HD_ + c4;
    if (j >= KTOK_) {
        *(uint2*)dst = make_uint2(0u, 0u);
        return;
    }
    int t = tokidx[b * 16 + j];
    uint2 ub = *(const uint2*)(kin + ((size_t)(b * T_) + t) * HD_ + c4);
    const __half* hb = (const __half*)&ub;
    float kb[4] = {__half2float(hb[0]), __half2float(hb[1]), __half2float(hb[2]), __half2float(hb[3])};
    float s[4] = {0.f, 0.f, 0.f, 0.f};
#pragma unroll
    for (int bb = 0; bb < B_; bb++) {
        uint2 u = *(const uint2*)(kin + ((size_t)(bb * T_) + t) * HD_ + c4);
        const __half* hp = (const __half*)&u;
        s[0] += __half2float(hp[0]); s[1] += __half2float(hp[1]);
        s[2] += __half2float(hp[2]); s[3] += __half2float(hp[3]);
    }
    const float w = STRENGTH_ * (1.f - ALPHA_);
    const float c7 = 1.f / (float)(B_ - 1);
    uint2 u;
    u.x = pack_h2(w * ((s[0] - kb[0]) * c7 - kb[0]), w * ((s[1] - kb[1]) * c7 - kb[1]));
    u.y = pack_h2(w * ((s[2] - kb[2]) * c7 - kb[2]), w * ((s[3] - kb[3]) * c7 - kb[3]));
    *(uint2*)dst = u;
}

// ---------------- pos partial reduce + top-k ----------------
__global__ void pos_reduce_k(const float* __restrict__ posp, float* __restrict__ scores)
{
    int idx = blockIdx.x * blockDim.x + threadIdx.x;
    if (idx >= B_ * S_) return;
    int b = idx / S_, s = idx % S_;
    float sum = 0.f;
#pragma unroll
    for (int h = 0; h < H_; h++) sum += posp[(size_t)(b * H_ + h) * S_ + s];
    scores[idx] = sum * (1.f / (float)H_);
}

__global__ __launch_bounds__(256) void pos_topk_k(const float* __restrict__ scores, int* __restrict__ mask)
{
    const int b = blockIdx.y;
    __shared__ float sc[S_];
    for (int i = threadIdx.x; i < S_; i += 256) sc[i] = scores[b * S_ + i];
    __syncthreads();
    const int i = blockIdx.x * 256 + threadIdx.x;
    float v = sc[i];
    int rank = 0;
    for (int j = 0; j < S_; j++) {
        float u = sc[j];
        rank += (int)((u > v) || (u == v && j < i));
    }
    mask[b * S_ + i] = (rank < KPOS_) ? 1 : 0;
}

// ---------------- V mixing ----------------
__global__ void vmix_k(const __half* __restrict__ vin, const int* __restrict__ tokmask,
                       __half* __restrict__ v2)
{
    int idx = blockIdx.x * blockDim.x + threadIdx.x;
    if (idx >= T_ * HD_) return;
    int t = idx / HD_;
    int c = idx % HD_;
    float vv[B_];
    float vsum = 0.f;
#pragma unroll
    for (int b = 0; b < B_; b++) {
        vv[b] = __half2float(vin[((size_t)(b * T_) + t) * HD_ + c]);
        vsum += vv[b];
    }
#pragma unroll
    for (int b = 0; b < B_; b++) {
        float tm = tokmask[b * T_ + t] ? STRENGTH_ : 0.f;
        float x  = vv[b];
        float mo = (vsum - x) * (1.f / (float)(B_ - 1));
        float mixed = ALPHA_ * x + (1.f - ALPHA_) * mo;
        v2[((size_t)(b * T_) + t) * HD_ + c] = __float2half_rn(x + tm * (mixed - x));
    }
}

// ====================================================================
//  attention pass 2 — Ph aliases the (dead-by-then) Qs/Ks region
// ====================================================================
#define VP_  72
#define PP_  88
#define KDP_ 24
#define CRP_ 18
#define A2_QS 0
#define A2_KS (A2_QS + 128 * QP_ * 2)        // 18432
#define A2_DK (A2_KS + 64 * KP2_ * 2)        // 29696
#define A2_VS (A2_DK + 64 * KDP_ * 2)        // 32768
#define A2_PS 0                              // alias over Qs+Ks (22528 <= 29696)
#define A2_MS (A2_VS + TP_ * VP_ * 2)        // 44288
#define A2_MI (A2_MS + TP_ * 4)              // 44608
#define A2_CR (A2_MI + TP_ * 4)              // 44928
#define A2_SMEM (A2_CR + 128 * CRP_ * 4)     // 54144

__global__ __launch_bounds__(256) void attn2_k(
    const __half* __restrict__ q, const __half* __restrict__ kk,
    const __half* __restrict__ dksel, const __half* __restrict__ v2,
    const int* __restrict__ tokmask, const int* __restrict__ maskidx,
    float* __restrict__ posp, __half* __restrict__ ctx)
{
    extern __shared__ char dsm[];
    __half* Qs = (__half*)(dsm + A2_QS);
    __half* Ks = (__half*)(dsm + A2_KS);
    __half* Dk = (__half*)(dsm + A2_DK);
    __half* Vs = (__half*)(dsm + A2_VS);
    __half* Ph = (__half*)(dsm + A2_PS);
    float*  Ms = (float*)(dsm + A2_MS);
    int*    Mi = (int*)(dsm + A2_MI);
    float*  Crs = (float*)(dsm + A2_CR);

    const int b = blockIdx.z, h = blockIdx.y;
    const int tid = threadIdx.x;
    const int wid = tid >> 5, lane = tid & 31;
    const int bm0 = blockIdx.x * 128;

#pragma unroll
    for (int i = 0; i < 4; i++) {
        int f = tid + i * 256;
        int row = f >> 3, c8 = (f & 7) * 8;
        uint4 v = *(const uint4*)(q + ((size_t)(b * S_) + bm0 + row) * HD_ + h * D_ + c8);
        *(uint4*)&Qs[row * QP_ + c8] = v;
    }
    for (int f = tid; f < 64 * KP2_ / 2; f += 256) ((uint32_t*)Ks)[f] = 0;
    for (int f = tid; f < 64 * KDP_ / 2; f += 256) ((uint32_t*)Dk)[f] = 0;
    for (int f = tid; f < TP_ * VP_ / 2; f += 256) ((uint32_t*)Vs)[f] = 0;
    if (tid < TP_) {
        Ms[tid] = (tid < T_) ? (float)tokmask[b * T_ + tid] : 0.f;
        Mi[tid] = maskidx[b * TP_ + tid];
    }
    __syncthreads();
    for (int f = tid; f < T_ * 16; f += 256) {
        int t = f >> 4, d4 = (f & 15) * 4;
        uint2 u = *(const uint2*)(kk + ((size_t)(b * T_) + t) * HD_ + h * D_ + d4);
        const __half* hp = (const __half*)&u;
        Ks[(d4 + 0) * KP2_ + t] = hp[0];
        Ks[(d4 + 1) * KP2_ + t] = hp[1];
        Ks[(d4 + 2) * KP2_ + t] = hp[2];
        Ks[(d4 + 3) * KP2_ + t] = hp[3];
    }
    for (int f = tid; f < T_ * 8; f += 256) {
        int t = f >> 3, d8 = (f & 7) * 8;
        *(uint4*)&Vs[t * VP_ + d8] =
            *(const uint4*)(v2 + ((size_t)(b * T_) + t) * HD_ + h * D_ + d8);
    }
    {
        int f = tid;
        int j = f >> 4, d4 = (f & 15) * 4;
        uint2 u = *(const uint2*)(dksel + ((size_t)(b * 16 + j)) * HD_ + h * D_ + d4);
        const __half* hp = (const __half*)&u;
        Dk[(d4 + 0) * KDP_ + j] = hp[0];
        Dk[(d4 + 1) * KDP_ + j] = hp[1];
        Dk[(d4 + 2) * KDP_ + j] = hp[2];
        Dk[(d4 + 3) * KDP_ + j] = hp[3];
    }
    __syncthreads();

    const int ltile = lane >> 3, lrit = lane & 7;
    const int a_m  = wid * 16 + (ltile & 1) * 8 + lrit;
    const int a_kc = (ltile >> 1) * 8;
    const int b_k  = (ltile & 1) * 8 + lrit;
    const int b_n  = (ltile >> 1) * 8;
    const int r0   = wid * 16 + (lane >> 2);

    float acc[10][4];
    float accc[2][4];
#pragma unroll
    for (int nt = 0; nt < 10; nt++)
#pragma unroll
        for (int r = 0; r < 4; r++) acc[nt][r] = 0.f;
#pragma unroll
    for (int nt = 0; nt < 2; nt++)
#pragma unroll
        for (int r = 0; r < 4; r++) accc[nt][r] = 0.f;

#pragma unroll
    for (int kkk = 0; kkk < 64; kkk += 16) {
        uint32_t af[4], bf[10][2];
        ldmx4(af, &Qs[a_m * QP_ + kkk + a_kc]);
#pragma unroll
        for (int p = 0; p < 5; p++) {
            uint32_t br[4];
            ldmx4t(br, &Ks[(kkk + b_k) * KP2_ + b_n + p * 16]);
            bf[2 * p][0]     = br[0];
            bf[2 * p][1]     = br[1];
            bf[2 * p + 1][0] = br[2];
            bf[2 * p + 1][1] = br[3];
        }
#pragma unroll
        for (int nt = 0; nt < 10; nt++)
            mma_f16(acc[nt], af, bf[nt]);
        {
            uint32_t br[4];
            ldmx4t(br, &Dk[(kkk + b_k) * KDP_ + b_n]);
            uint32_t c0[2] = {br[0], br[1]};
            uint32_t c1[2] = {br[2], br[3]};
            mma_f16(accc[0], af, c0);
            mma_f16(accc[1], af, c1);
        }
    }

#pragma unroll
    for (int nt = 0; nt < 2; nt++) {
        int ccol = nt * 8 + 2 * (lane & 3);
        Crs[r0 * CRP_ + ccol]           = accc[nt][0];
        Crs[r0 * CRP_ + ccol + 1]       = accc[nt][1];
        Crs[(r0 + 8) * CRP_ + ccol]     = accc[nt][2];
        Crs[(r0 + 8) * CRP_ + ccol + 1] = accc[nt][3];
    }
    __syncwarp();

    float rsA_a = 0.f, rsA_b = 0.f, msA_a = 0.f, msA_b = 0.f;
    float rs2_a = 0.f, rs2_b = 0.f;
#pragma unroll
    for (int nt = 0; nt < 10; nt++) {
        int col = nt * 8 + 2 * (lane & 3);
        float m0 = Ms[col], m1 = Ms[col + 1];
        int j0 = Mi[col], j1 = Mi[col + 1];
        float l0 = acc[nt][0], l1 = acc[nt][1], l2 = acc[nt][2], l3 = acc[nt][3];
        float e0 = (col     < T_) ? __expf(l0 * SCALE_) : 0.f;
        float e1 = (col + 1 < T_) ? __expf(l1 * SCALE_) : 0.f;
        float e2 = (col     < T_) ? __expf(l2 * SCALE_) : 0.f;
        float e3 = (col + 1 < T_) ? __expf(l3 * SCALE_) : 0.f;
        rsA_a += e0 + e1; rsA_b += e2 + e3;
        msA_a += e0 * m0 + e1 * m1;
        msA_b += e2 * m0 + e3 * m1;
        float f0 = (j0 >= 0) ? __expf((l0 + Crs[r0 * CRP_ + j0]) * SCALE_) : e0;
        float f1 = (j1 >= 0) ? __expf((l1 + Crs[r0 * CRP_ + j1]) * SCALE_) : e1;
        float f2 = (j0 >= 0) ? __expf((l2 + Crs[(r0 + 8) * CRP_ + j0]) * SCALE_) : e2;
        float f3 = (j1 >= 0) ? __expf((l3 + Crs[(r0 + 8) * CRP_ + j1]) * SCALE_) : e3;
        rs2_a += f0 + f1; rs2_b += f2 + f3;
        acc[nt][0] = f0; acc[nt][1] = f1; acc[nt][2] = f2; acc[nt][3] = f3;
    }
    rsA_a += __shfl_xor_sync(0xffffffffu, rsA_a, 1);
    rsA_a += __shfl_xor_sync(0xffffffffu, rsA_a, 2);
    rsA_b += __shfl_xor_sync(0xffffffffu, rsA_b, 1);
    rsA_b += __shfl_xor_sync(0xffffffffu, rsA_b, 2);
    msA_a += __shfl_xor_sync(0xffffffffu, msA_a, 1);
    msA_a += __shfl_xor_sync(0xffffffffu, msA_a, 2);
    msA_b += __shfl_xor_sync(0xffffffffu, msA_b, 1);
    msA_b += __shfl_xor_sync(0xffffffffu, msA_b, 2);
    rs2_a += __shfl_xor_sync(0xffffffffu, rs2_a, 1);
    rs2_a += __shfl_xor_sync(0xffffffffu, rs2_a, 2);
    rs2_b += __shfl_xor_sync(0xffffffffu, rs2_b, 1);
    rs2_b += __shfl_xor_sync(0xffffffffu, rs2_b, 2);

    if ((lane & 3) == 0) {
        const size_t pb2 = (size_t)(b * H_ + h) * S_ + bm0;
        posp[pb2 + r0]     = msA_a / rsA_a;
        posp[pb2 + r0 + 8] = msA_b / rsA_b;
    }

    // all Qs/Ks reads done across the block before Ph (aliased) is written
    __syncthreads();

    float inv_a = 1.f / rs2_a;
    float inv_b = 1.f / rs2_b;
#pragma unroll
    for (int nt = 0; nt < 10; nt++) {
        int col = nt * 8 + 2 * (lane & 3);
        *(uint32_t*)&Ph[r0 * PP_ + col] =
            pack_h2(acc[nt][0] * inv_a, acc[nt][1] * inv_a);
        *(uint32_t*)&Ph[(r0 + 8) * PP_ + col] =
            pack_h2(acc[nt][2] * inv_b, acc[nt][3] * inv_b);
    }
    __syncthreads();

    float acc2[8][4];
#pragma unroll
    for (int nt = 0; nt < 8; nt++)
#pragma unroll
        for (int r = 0; r < 4; r++) acc2[nt][r] = 0.f;

#pragma unroll
    for (int kkk = 0; kkk < TP_; kkk += 16) {
        uint32_t af[4], bf[8][2];
        ldmx4(af, &Ph[a_m * PP_ + kkk + a_kc]);
#pragma unroll
        for (int p = 0; p < 4; p++) {
            uint32_t br[4];
            ldmx4t(br, &Vs[(kkk + b_k) * VP_ + b_n + p * 16]);
            bf[2 * p][0]     = br[0];
            bf[2 * p][1]     = br[1];
            bf[2 * p + 1][0] = br[2];
            bf[2 * p + 1][1] = br[3];
        }
#pragma unroll
        for (int nt = 0; nt < 8; nt++)
            mma_f16(acc2[nt], af, bf[nt]);
    }

#pragma unroll
    for (int nt = 0; nt < 8; nt++) {
        int col = nt * 8 + 2 * (lane & 3);
        *(uint32_t*)(ctx + ((size_t)(b * S_) + bm0 + r0) * HD_ + h * D_ + col) =
            pack_h2(acc2[nt][0], acc2[nt][1]);
        *(uint32_t*)(ctx + ((size_t)(b * S_) + bm0 + r0 + 8) * HD_ + h * D_ + col) =
            pack_h2(acc2[nt][2], acc2[nt][3]);
    }
}

// ---------------- fused batch-sum + patch injection (2 groups/thread) ----------------
#define NG8_ (S_ * HD_ / 8)
__global__ __launch_bounds__(256) void inject_fused_k(
    __half* __restrict__ ctx, const int* __restrict__ posmask)
{
    const int g = blockIdx.x * 256 + threadIdx.x;
    if (g >= NG8_ / 2) return;
#pragma unroll
    for (int half = 0; half < 2; half++) {
        const int i8 = g + half * (NG8_ / 2);
        const size_t base = (size_t)i8 * 8;
        const int s = (int)(base / HD_);

        float v[B_][8];
        float sum[8] = {0.f, 0.f, 0.f, 0.f, 0.f, 0.f, 0.f, 0.f};
#pragma unroll
        for (int b = 0; b < B_; b++) {
            uint4 u = *(const uint4*)(ctx + (size_t)b * S_ * HD_ + base);
            float2 f0 = __half22float2(*(__half2*)&u.x);
            float2 f1 = __half22float2(*(__half2*)&u.y);
            float2 f2 = __half22float2(*(__half2*)&u.z);
            float2 f3 = __half22float2(*(__half2*)&u.w);
            v[b][0] = f0.x; v[b][1] = f0.y; v[b][2] = f1.x; v[b][3] = f1.y;
            v[b][4] = f2.x; v[b][5] = f2.y; v[b][6] = f3.x; v[b][7] = f3.y;
#pragma unroll
            for (int j = 0; j < 8; j++) sum[j] += v[b][j];
        }
        const float c7 = 1.f / (float)(B_ - 1);
#pragma unroll
        for (int b = 0; b < B_; b++) {
            if (posmask[b * S_ + s]) {
                float o[8];
#pragma unroll
                for (int j = 0; j < 8; j++)
                    o[j] = v[b][j] + WINJ_ * ((sum[j] - v[b][j]) * c7 - v[b][j]);
                uint4 u;
                u.x = pack_h2(o[0], o[1]);
                u.y = pack_h2(o[2], o[3]);
                u.z = pack_h2(o[4], o[5]);
                u.w = pack_h2(o[6], o[7]);
                *(uint4*)(ctx + (size_t)b * S_ * HD_ + base) = u;
            }
        }
    }
}

// ---------------- launch ----------------
extern "C" void kernel_launch(void* const* d_in, const int* in_sizes, int n_in,
                              void* d_out, int out_size)
{
    (void)in_sizes; (void)n_in; (void)out_size;
    const float* X  = (const float*)d_in[0];
    const float* E  = (const float*)d_in[1];
    const float* Wq = (const float*)d_in[2];
    const float* Wk = (const float*)d_in[3];
    const float* Wv = (const float*)d_in[4];
    const float* Wo = (const float*)d_in[5];
    const float* bo = (const float*)d_in[6];
    float* out = (float*)d_out;

    __half *x16, *e16, *wq16, *wk16, *wv16, *wo16, *q, *k16, *v16, *v216, *dksel, *ctx;
    float *posp, *tokpart, *posscores;
    int *tokmask, *posmask, *tokidx, *maskidx;
    cudaGetSymbolAddress((void**)&x16,      g_x16);
    cudaGetSymbolAddress((void**)&e16,      g_e16);
    cudaGetSymbolAddress((void**)&wq16,     g_wq16);
    cudaGetSymbolAddress((void**)&wk16,     g_wk16);
    cudaGetSymbolAddress((void**)&wv16,     g_wv16);
    cudaGetSymbolAddress((void**)&wo16,     g_wo16);
    cudaGetSymbolAddress((void**)&q,        g_q);
    cudaGetSymbolAddress((void**)&k16,      g_k16);
    cudaGetSymbolAddress((void**)&v16,      g_v16);
    cudaGetSymbolAddress((void**)&v216,     g_v216);
    cudaGetSymbolAddress((void**)&dksel,    g_dksel);
    cudaGetSymbolAddress((void**)&tokidx,   g_tokidx);
    cudaGetSymbolAddress((void**)&maskidx,  g_maskidx);
    cudaGetSymbolAddress((void**)&posp,     g_posp);
    cudaGetSymbolAddress((void**)&tokpart,  g_tokpart);
    cudaGetSymbolAddress((void**)&tokmask,  g_tokmask);
    cudaGetSymbolAddress((void**)&posscores,g_posscores);
    cudaGetSymbolAddress((void**)&posmask,  g_posmask);
    cudaGetSymbolAddress((void**)&ctx,      g_ctx);

    cudaFuncSetAttribute(attn2_k, cudaFuncAttributeMaxDynamicSharedMemorySize, A2_SMEM);
    cudaFuncSetAttribute(hgemm16_k<1, 0>, cudaFuncAttributeMaxDynamicSharedMemorySize, GSM_TOTAL);
    cudaFuncSetAttribute(hgemm16_k<0, 1>, cudaFuncAttributeMaxDynamicSharedMemorySize, GSM_TOTAL);

    static cudaStream_t s2 = nullptr, s3 = nullptr;
    static cudaEvent_t evA = nullptr, evB = nullptr, evW = nullptr, evC2 = nullptr;
    static cudaEvent_t evTok = nullptr, evDk = nullptr;
    if (s2 == nullptr) {
        cudaStreamCreateWithFlags(&s2, cudaStreamNonBlocking);
        cudaStreamCreateWithFlags(&s3, cudaStreamNonBlocking);
        cudaEventCreateWithFlags(&evA, cudaEventDisableTiming);
        cudaEventCreateWithFlags(&evB, cudaEventDisableTiming);
        cudaEventCreateWithFlags(&evW, cudaEventDisableTiming);
        cudaEventCreateWithFlags(&evC2, cudaEventDisableTiming);
        cudaEventCreateWithFlags(&evTok, cudaEventDisableTiming);
        cudaEventCreateWithFlags(&evDk, cudaEventDisableTiming);
    }

    const int MH = B_ * S_ / 2;
    const int XH4 = MH * C_ / 4;

    // fork A: side stream s2 — Wq weight cvt first, then E/W cvts + K/V projections
    cudaEventRecord(evA, 0);
    cudaStreamWaitEvent(s2, evA, 0);
    cudaStreamWaitEvent(s3, evA, 0);
    cvt16_k<<<(C_ * HD_ / 4 + 255) / 256, 256, 0, s2>>>(Wq, wq16, C_ * HD_ / 4);
    cudaEventRecord(evW, s2);
    cvt16_k<<<(B_ * T_ * CE_ / 4 + 255) / 256, 256, 0, s2>>>(E, e16, B_ * T_ * CE_ / 4);
    cvt16_k<<<(CE_ * HD_ / 4 + 255) / 256, 256, 0, s2>>>(Wk, wk16, CE_ * HD_ / 4);
    cvt16_k<<<(CE_ * HD_ / 4 + 255) / 256, 256, 0, s2>>>(Wv, wv16, CE_ * HD_ / 4);
    cvt16_k<<<(HD_ * C_ / 4 + 255) / 256, 256, 0, s2>>>(Wo, wo16, HD_ * C_ / 4);
    hgemm16_k<1, 0><<<dim3(HD_ / 128, (B_ * T_ + 127) / 128), 256, GSM_TOTAL, s2>>>(
        e16, wk16, k16, B_ * T_, HD_, CE_, nullptr, nullptr);
    hgemm16_k<1, 0><<<dim3(HD_ / 128, (B_ * T_ + 127) / 128), 256, GSM_TOTAL, s2>>>(
        e16, wv16, v16, B_ * T_, HD_, CE_, nullptr, nullptr);
    cudaEventRecord(evB, s2);

    // fork B: s3 converts X half 2 concurrent with main's half-1 cvt + Wq half-1
    cvt16_k<<<(XH4 + 255) / 256, 256, 0, s3>>>(X + (size_t)MH * C_, x16 + (size_t)MH * C_, XH4);
    cudaEventRecord(evC2, s3);

    // main: X half-1 cvt, then Wq in two M-halves
    cvt16_k<<<(XH4 + 255) / 256, 256>>>(X, x16, XH4);
    cudaStreamWaitEvent(0, evW, 0);
    hgemm16_k<1, 0><<<dim3(HD_ / 128, MH / 128), 256, GSM_TOTAL>>>(
        x16, wq16, q, MH, HD_, C_, nullptr, nullptr);
    cudaStreamWaitEvent(0, evC2, 0);
    hgemm16_k<1, 0><<<dim3(HD_ / 128, MH / 128), 256, GSM_TOTAL>>>(
        x16 + (size_t)MH * C_, wq16, q + (size_t)MH * HD_, MH, HD_, C_, nullptr, nullptr);
    cudaStreamWaitEvent(0, evB, 0);

    // attn pass 1 -> fused token reduce/top-k/compact maps
    attn1_k<<<dim3(SCHUNK_, H_, B_), 256>>>(q, k16, tokpart);
    tok_topk_k<<<B_, 128>>>(tokpart, tokmask, tokidx, maskidx);
    cudaEventRecord(evTok, 0);

    // dksel on s2 concurrent with vmix on main
    cudaStreamWaitEvent(s2, evTok, 0);
    dksel_k<<<(B_ * 16 * (HD_ / 4) + 255) / 256, 256, 0, s2>>>(k16, tokidx, dksel);
    cudaEventRecord(evDk, s2);
    vmix_k<<<(T_ * HD_ + 255) / 256, 256>>>(v16, tokmask, v216);
    cudaStreamWaitEvent(0, evDk, 0);

    // attn pass 2 -> pos partials + fp16 ctx
    attn2_k<<<dim3(SCHUNK_, H_, B_), 256, A2_SMEM>>>(q, k16, dksel, v216, tokmask, maskidx, posp, ctx);

    // pos mask
    pos_reduce_k<<<(B_ * S_ + 255) / 256, 256>>>(posp, posscores);
    pos_topk_k<<<dim3(S_ / 256, B_), 256>>>(posscores, posmask);

    // injection
    inject_fused_k<<<(NG8_ / 2 + 255) / 256, 256>>>(ctx, posmask);

    // output projection + bias + fp16 residual
    hgemm16_k<0, 1><<<dim3(HD_ / 128, (B_ * S_) / 128), 256, GSM_TOTAL>>>(
        ctx, wo16, out, B_ * S_, HD_, C_, bo, x16);
}

// round 17
// speedup vs baseline: 1.0092x; 1.0084x over previous
#include <cuda_runtime.h>
#include <cuda_fp16.h>
#include <math.h>
#include <stdint.h>

#define B_  8
#define S_  4096
#define T_  77
#define TP_ 80
#define C_  1280
#define CE_ 2048
#define H_  20
#define D_  64
#define HD_ 1280
#define KTOK_ 12
#define KPOS_ 1229
#define SCHUNK_ (S_/128)   // 32

#define SCALE_ 0.125f
#define STRENGTH_ 0.5f
#define ALPHA_ 0.7f
#define WINJ_ 0.25f

// ---------------- scratch ----------------
__device__ __half g_x16[(size_t)B_*S_*C_];
__device__ __half g_e16[B_*T_*CE_];
__device__ __half g_wq16[C_*HD_];
__device__ __half g_wk16[CE_*HD_];
__device__ __half g_wv16[CE_*HD_];
__device__ __half g_wo16[HD_*C_];
__device__ __half g_q[(size_t)B_*S_*HD_];
__device__ __half g_k16[B_*T_*HD_];
__device__ __half g_v16[B_*T_*HD_];
__device__ __half g_v216[B_*T_*HD_];
__device__ __half g_dksel[B_*16*HD_];
__device__ int   g_tokidx[B_*16];
__device__ int   g_maskidx[B_*TP_];
__device__ float g_posp[B_*H_*S_];
__device__ float g_tokpart[B_*H_*SCHUNK_*T_];
__device__ int   g_tokmask[B_*T_];
__device__ float g_posscores[B_*S_];
__device__ int   g_posmask[B_*S_];
__device__ __half g_ctx[(size_t)B_*S_*HD_];

// ---------------- helpers ----------------
__device__ __forceinline__ void mma_f16(float* c, const uint32_t* a, const uint32_t* b) {
    asm volatile(
        "mma.sync.aligned.m16n8k16.row.col.f32.f16.f16.f32 "
        "{%0,%1,%2,%3},{%4,%5,%6,%7},{%8,%9},{%0,%1,%2,%3};"
        : "+f"(c[0]), "+f"(c[1]), "+f"(c[2]), "+f"(c[3])
        : "r"(a[0]), "r"(a[1]), "r"(a[2]), "r"(a[3]), "r"(b[0]), "r"(b[1]));
}
__device__ __forceinline__ void ldmx4(uint32_t* r, const void* p) {
    uint32_t a = (uint32_t)__cvta_generic_to_shared(p);
    asm volatile("ldmatrix.sync.aligned.m8n8.x4.shared.b16 {%0,%1,%2,%3}, [%4];"
                 : "=r"(r[0]), "=r"(r[1]), "=r"(r[2]), "=r"(r[3]) : "r"(a));
}
__device__ __forceinline__ void ldmx4t(uint32_t* r, const void* p) {
    uint32_t a = (uint32_t)__cvta_generic_to_shared(p);
    asm volatile("ldmatrix.sync.aligned.m8n8.x4.trans.shared.b16 {%0,%1,%2,%3}, [%4];"
                 : "=r"(r[0]), "=r"(r[1]), "=r"(r[2]), "=r"(r[3]) : "r"(a));
}
__device__ __forceinline__ uint32_t pack_h2(float x, float y) {
    __half2 h = __floats2half2_rn(x, y);
    return *(uint32_t*)&h;
}
__device__ __forceinline__ void cpa16(uint32_t dst, const void* src, int sz) {
    asm volatile("cp.async.ca.shared.global [%0], [%1], 16, %2;"
                 :: "r"(dst), "l"(src), "r"(sz));
}

// ---------------- fp32 -> fp16 conversion ----------------
__global__ __launch_bounds__(256) void cvt16_k(
    const float* __restrict__ src, __half* __restrict__ dst, int n4)
{
    int i = blockIdx.x * 256 + threadIdx.x;
    if (i >= n4) return;
    float4 v = *(const float4*)(src + (size_t)i * 4);
    uint2 u; u.x = pack_h2(v.x, v.y); u.y = pack_h2(v.z, v.w);
    *(uint2*)(dst + (size_t)i * 4) = u;
}

// ====================================================================
//  pure-fp16 GEMM : 128x128x64 tiles, cp.async double-buffered
// ====================================================================
#define GA_P 72
#define GB_P 136
#define GSM_AS 0
#define GSM_BS (2 * 128 * GA_P * 2)
#define GSM_TOTAL (GSM_BS + 2 * 64 * GB_P * 2)

template<int OUT16, int EPI>
__global__ __launch_bounds__(256) void hgemm16_k(
    const __half* __restrict__ A, const __half* __restrict__ Bm, void* __restrict__ Cm,
    int M, int N, int K,
    const float* __restrict__ bias, const __half* __restrict__ resid16)
{
    extern __shared__ char gsm[];
    __half* As = (__half*)(gsm + GSM_AS);
    __half* Bs = (__half*)(gsm + GSM_BS);

    const int tid = threadIdx.x;
    const int wid = tid >> 5, lane = tid & 31;
    const int wm = wid & 1, wn = wid >> 1;
    const int bm0 = blockIdx.y * 128, bn0 = blockIdx.x * 128;

    float acc[4][4][4];
#pragma unroll
    for (int i = 0; i < 4; i++)
#pragma unroll
        for (int j = 0; j < 4; j++)
#pragma unroll
            for (int r = 0; r < 4; r++) acc[i][j][r] = 0.f;

    const int ltile = lane >> 3, lrit = lane & 7;
    const int a_m  = wm * 64 + (ltile & 1) * 8 + lrit;
    const int a_kc = (ltile >> 1) * 8;
    const int b_k  = (ltile & 1) * 8 + lrit;
    const int b_n  = wn * 32 + (ltile >> 1) * 8;

#define G_ISSUE(k0, buf)                                                             \
    {                                                                                \
        _Pragma("unroll")                                                            \
        for (int i = 0; i < 4; i++) {                                                \
            int cid = tid + i * 256;                                                 \
            int ar = cid >> 3, ach = (cid & 7) * 8;                                  \
            cpa16((uint32_t)__cvta_generic_to_shared(                                \
                      &As[(size_t)(buf) * 128 * GA_P + ar * GA_P + ach]),            \
                  A + (size_t)(bm0 + ar) * K + (k0) + ach, (bm0 + ar < M) ? 16 : 0); \
            int bk = cid >> 4, bch = (cid & 15) * 8;                                 \
            cpa16((uint32_t)__cvta_generic_to_shared(                                \
                      &Bs[(size_t)(buf) * 64 * GB_P + bk * GB_P + bch]),             \
                  Bm + (size_t)((k0) + bk) * N + bn0 + bch, 16);                     \
        }                                                                            \
        asm volatile("cp.async.commit_group;");                                      \
    }

    G_ISSUE(0, 0);
    const int KT = K >> 6;
    int rbuf = 0;
    for (int kt = 0; kt < KT; kt++) {
        if (kt + 1 < KT) {
            G_ISSUE((kt + 1) << 6, rbuf ^ 1);
            asm volatile("cp.async.wait_group 1;");
        } else {
            asm volatile("cp.async.wait_group 0;");
        }
        __syncthreads();

        const __half* Ab = &As[(size_t)rbuf * 128 * GA_P];
        const __half* Bb = &Bs[(size_t)rbuf * 64 * GB_P];
#pragma unroll
        for (int kk = 0; kk < 64; kk += 16) {
            uint32_t af[4][4], bf[4][2];
#pragma unroll
            for (int mt = 0; mt < 4; mt++)
                ldmx4(af[mt], &Ab[(a_m + mt * 16) * GA_P + kk + a_kc]);
#pragma unroll
            for (int p = 0; p < 2; p++) {
                uint32_t br[4];
                ldmx4t(br, &Bb[(kk + b_k) * GB_P + b_n + p * 16]);
                bf[2 * p][0]     = br[0];
                bf[2 * p][1]     = br[1];
                bf[2 * p + 1][0] = br[2];
                bf[2 * p + 1][1] = br[3];
            }
#pragma unroll
            for (int mt = 0; mt < 4; mt++)
#pragma unroll
                for (int nt = 0; nt < 4; nt++)
                    mma_f16(acc[mt][nt], af[mt], bf[nt]);
        }
        __syncthreads();
        rbuf ^= 1;
    }
#undef G_ISSUE

    const int row0 = bm0 + wm * 64 + (lane >> 2);
    const int col0 = bn0 + wn * 32 + 2 * (lane & 3);
#pragma unroll
    for (int mt = 0; mt < 4; mt++) {
#pragma unroll
        for (int nt = 0; nt < 4; nt++) {
            int r = row0 + mt * 16;
            int c = col0 + nt * 8;
            if (OUT16) {
                if (r < M)
                    *(uint32_t*)((__half*)Cm + (size_t)r * N + c) = pack_h2(acc[mt][nt][0], acc[mt][nt][1]);
                if (r + 8 < M)
                    *(uint32_t*)((__half*)Cm + (size_t)(r + 8) * N + c) = pack_h2(acc[mt][nt][2], acc[mt][nt][3]);
            } else {
                float v0 = acc[mt][nt][0], v1 = acc[mt][nt][1];
                float v2 = acc[mt][nt][2], v3 = acc[mt][nt][3];
                if (EPI) {
                    float b0v = bias[c], b1v = bias[c + 1];
                    if (r < M) {
                        uint32_t u = *(const uint32_t*)(resid16 + (size_t)r * N + c);
                        float2 rr = __half22float2(*(__half2*)&u);
                        v0 += b0v + rr.x; v1 += b1v + rr.y;
                    }
                    if (r + 8 < M) {
                        uint32_t u = *(const uint32_t*)(resid16 + (size_t)(r + 8) * N + c);
                        float2 rr = __half22float2(*(__half2*)&u);
                        v2 += b0v + rr.x; v3 += b1v + rr.y;
                    }
                }
                if (r < M) { float2 o; o.x = v0; o.y = v1; *(float2*)((float*)Cm + (size_t)r * N + c) = o; }
                if (r + 8 < M) { float2 o; o.x = v2; o.y = v3; *(float2*)((float*)Cm + (size_t)(r + 8) * N + c) = o; }
            }
        }
    }
}

// ====================================================================
//  attention pass 1 (b0 = batch offset for split launches)
// ====================================================================
#define QP_  72
#define KP2_ 88

__global__ __launch_bounds__(256) void attn1_k(
    const __half* __restrict__ q, const __half* __restrict__ kk,
    float* __restrict__ tokpart, int b0)
{
    __shared__ __half Qs[128 * QP_];
    __shared__ __half Ks[64 * KP2_];
    __shared__ float tpw[8][TP_];

    const int b = blockIdx.z + b0, h = blockIdx.y;
    const int tid = threadIdx.x;
    const int wid = tid >> 5, lane = tid & 31;
    const int bm0 = blockIdx.x * 128;

#pragma unroll
    for (int i = 0; i < 4; i++) {
        int f = tid + i * 256;
        int row = f >> 3, c8 = (f & 7) * 8;
        uint4 v = *(const uint4*)(q + ((size_t)(b * S_) + bm0 + row) * HD_ + h * D_ + c8);
        *(uint4*)&Qs[row * QP_ + c8] = v;
    }
    for (int f = tid; f < 64 * KP2_ / 2; f += 256) ((uint32_t*)Ks)[f] = 0;
    __syncthreads();
    for (int f = tid; f < T_ * 16; f += 256) {
        int t = f >> 4, d4 = (f & 15) * 4;
        uint2 u = *(const uint2*)(kk + ((size_t)(b * T_) + t) * HD_ + h * D_ + d4);
        const __half* hp = (const __half*)&u;
        Ks[(d4 + 0) * KP2_ + t] = hp[0];
        Ks[(d4 + 1) * KP2_ + t] = hp[1];
        Ks[(d4 + 2) * KP2_ + t] = hp[2];
        Ks[(d4 + 3) * KP2_ + t] = hp[3];
    }
    __syncthreads();

    const int ltile = lane >> 3, lrit = lane & 7;
    const int a_m  = wid * 16 + (ltile & 1) * 8 + lrit;
    const int a_kc = (ltile >> 1) * 8;
    const int b_k  = (ltile & 1) * 8 + lrit;
    const int b_n  = (ltile >> 1) * 8;

    float acc[10][4];
#pragma unroll
    for (int nt = 0; nt < 10; nt++)
#pragma unroll
        for (int r = 0; r < 4; r++) acc[nt][r] = 0.f;

#pragma unroll
    for (int kkk = 0; kkk < 64; kkk += 16) {
        uint32_t af[4], bf[10][2];
        ldmx4(af, &Qs[a_m * QP_ + kkk + a_kc]);
#pragma unroll
        for (int p = 0; p < 5; p++) {
            uint32_t br[4];
            ldmx4t(br, &Ks[(kkk + b_k) * KP2_ + b_n + p * 16]);
            bf[2 * p][0]     = br[0];
            bf[2 * p][1]     = br[1];
            bf[2 * p + 1][0] = br[2];
            bf[2 * p + 1][1] = br[3];
        }
#pragma unroll
        for (int nt = 0; nt < 10; nt++)
            mma_f16(acc[nt], af, bf[nt]);
    }

    float rs_a = 0.f, rs_b = 0.f;
#pragma unroll
    for (int nt = 0; nt < 10; nt++) {
        int col = nt * 8 + 2 * (lane & 3);
        float e0 = (col     < T_) ? __expf(acc[nt][0] * SCALE_) : 0.f;
        float e1 = (col + 1 < T_) ? __expf(acc[nt][1] * SCALE_) : 0.f;
        float e2 = (col     < T_) ? __expf(acc[nt][2] * SCALE_) : 0.f;
        float e3 = (col + 1 < T_) ? __expf(acc[nt][3] * SCALE_) : 0.f;
        acc[nt][0] = e0; acc[nt][1] = e1; acc[nt][2] = e2; acc[nt][3] = e3;
        rs_a += e0 + e1;
        rs_b += e2 + e3;
    }
    rs_a += __shfl_xor_sync(0xffffffffu, rs_a, 1);
    rs_a += __shfl_xor_sync(0xffffffffu, rs_a, 2);
    rs_b += __shfl_xor_sync(0xffffffffu, rs_b, 1);
    rs_b += __shfl_xor_sync(0xffffffffu, rs_b, 2);
    float inv_a = 1.f / rs_a;
    float inv_b = 1.f / rs_b;

#pragma unroll
    for (int nt = 0; nt < 10; nt++) {
        float cs0 = acc[nt][0] * inv_a + acc[nt][2] * inv_b;
        float cs1 = acc[nt][1] * inv_a + acc[nt][3] * inv_b;
#pragma unroll
        for (int o = 4; o <= 16; o <<= 1) {
            cs0 += __shfl_xor_sync(0xffffffffu, cs0, o);
            cs1 += __shfl_xor_sync(0xffffffffu, cs1, o);
        }
        if (lane < 4) {
            int col = nt * 8 + 2 * lane;
            tpw[wid][col]     = cs0;
            tpw[wid][col + 1] = cs1;
        }
    }
    __syncthreads();
    if (tid < T_) {
        float s = 0.f;
#pragma unroll
        for (int w = 0; w < 8; w++) s += tpw[w][tid];
        int lin = (b * H_ + h) * SCHUNK_ + blockIdx.x;
        tokpart[(size_t)lin * T_ + tid] = s;
    }
}

// ---------------- fused token reduce + top-k + compact maps ----------------
__global__ void tok_topk_k(const float* __restrict__ tokpart, int* __restrict__ mask,
                           int* __restrict__ tokidx, int* __restrict__ maskidx)
{
    int b = blockIdx.x, tid = threadIdx.x;
    __shared__ float sc[T_];
    __shared__ int rk[T_];
    if (tid < T_) {
        float sum = 0.f;
        const float* tp = tokpart + (size_t)b * H_ * SCHUNK_ * T_ + tid;
        for (int hc = 0; hc < H_ * SCHUNK_; hc++)
            sum += tp[(size_t)hc * T_];
        sc[tid] = sum;
    }
    __syncthreads();
    if (tid < T_) {
        float v = sc[tid];
        int rank = 0;
        for (int j = 0; j < T_; j++) {
            float u = sc[j];
            rank += (int)((u > v) || (u == v && j < tid));
        }
        rk[tid] = rank;
        mask[b * T_ + tid] = (rank < KTOK_) ? 1 : 0;
    }
    __syncthreads();
    if (tid < TP_) {
        if (tid < T_) {
            int j = 0;
            for (int jj = 0; jj < tid; jj++) j += (rk[jj] < KTOK_);
            bool m = rk[tid] < KTOK_;
            maskidx[b * TP_ + tid] = m ? j : -1;
            if (m) tokidx[b * 16 + j] = tid;
        } else {
            maskidx[b * TP_ + tid] = -1;
        }
    }
}

// ---------------- compact dK ----------------
__global__ void dksel_k(const __half* __restrict__ kin, const int* __restrict__ tokidx,
                        __half* __restrict__ dksel)
{
    int idx = blockIdx.x * blockDim.x + threadIdx.x;
    if (idx >= B_ * 16 * (HD_ / 4)) return;
    int c4 = (idx % (HD_ / 4)) * 4;
    int rem = idx / (HD_ / 4);
    int j = rem % 16, b = rem / 16;
    __half* dst = dksel + ((size_t)(b * 16 + j)) * HD_ + c4;
    if (j >= KTOK_) {
        *(uint2*)dst = make_uint2(0u, 0u);
        return;
    }
    int t = tokidx[b * 16 + j];
    uint2 ub = *(const uint2*)(kin + ((size_t)(b * T_) + t) * HD_ + c4);
    const __half* hb = (const __half*)&ub;
    float kb[4] = {__half2float(hb[0]), __half2float(hb[1]), __half2float(hb[2]), __half2float(hb[3])};
    float s[4] = {0.f, 0.f, 0.f, 0.f};
#pragma unroll
    for (int bb = 0; bb < B_; bb++) {
        uint2 u = *(const uint2*)(kin + ((size_t)(bb * T_) + t) * HD_ + c4);
        const __half* hp = (const __half*)&u;
        s[0] += __half2float(hp[0]); s[1] += __half2float(hp[1]);
        s[2] += __half2float(hp[2]); s[3] += __half2float(hp[3]);
    }
    const float w = STRENGTH_ * (1.f - ALPHA_);
    const float c7 = 1.f / (float)(B_ - 1);
    uint2 u;
    u.x = pack_h2(w * ((s[0] - kb[0]) * c7 - kb[0]), w * ((s[1] - kb[1]) * c7 - kb[1]));
    u.y = pack_h2(w * ((s[2] - kb[2]) * c7 - kb[2]), w * ((s[3] - kb[3]) * c7 - kb[3]));
    *(uint2*)dst = u;
}

// ---------------- pos partial reduce + top-k ----------------
__global__ void pos_reduce_k(const float* __restrict__ posp, float* __restrict__ scores)
{
    int idx = blockIdx.x * blockDim.x + threadIdx.x;
    if (idx >= B_ * S_) return;
    int b = idx / S_, s = idx % S_;
    float sum = 0.f;
#pragma unroll
    for (int h = 0; h < H_; h++) sum += posp[(size_t)(b * H_ + h) * S_ + s];
    scores[idx] = sum * (1.f / (float)H_);
}

__global__ __launch_bounds__(256) void pos_topk_k(const float* __restrict__ scores, int* __restrict__ mask)
{
    const int b = blockIdx.y;
    __shared__ float sc[S_];
    for (int i = threadIdx.x; i < S_; i += 256) sc[i] = scores[b * S_ + i];
    __syncthreads();
    const int i = blockIdx.x * 256 + threadIdx.x;
    float v = sc[i];
    int rank = 0;
    for (int j = 0; j < S_; j++) {
        float u = sc[j];
        rank += (int)((u > v) || (u == v && j < i));
    }
    mask[b * S_ + i] = (rank < KPOS_) ? 1 : 0;
}

// ---------------- V mixing ----------------
__global__ void vmix_k(const __half* __restrict__ vin, const int* __restrict__ tokmask,
                       __half* __restrict__ v2)
{
    int idx = blockIdx.x * blockDim.x + threadIdx.x;
    if (idx >= T_ * HD_) return;
    int t = idx / HD_;
    int c = idx % HD_;
    float vv[B_];
    float vsum = 0.f;
#pragma unroll
    for (int b = 0; b < B_; b++) {
        vv[b] = __half2float(vin[((size_t)(b * T_) + t) * HD_ + c]);
        vsum += vv[b];
    }
#pragma unroll
    for (int b = 0; b < B_; b++) {
        float tm = tokmask[b * T_ + t] ? STRENGTH_ : 0.f;
        float x  = vv[b];
        float mo = (vsum - x) * (1.f / (float)(B_ - 1));
        float mixed = ALPHA_ * x + (1.f - ALPHA_) * mo;
        v2[((size_t)(b * T_) + t) * HD_ + c] = __float2half_rn(x + tm * (mixed - x));
    }
}

// ====================================================================
//  attention pass 2 — Ph aliases the (dead-by-then) Qs/Ks region
// ====================================================================
#define VP_  72
#define PP_  88
#define KDP_ 24
#define CRP_ 18
#define A2_QS 0
#define A2_KS (A2_QS + 128 * QP_ * 2)        // 18432
#define A2_DK (A2_KS + 64 * KP2_ * 2)        // 29696
#define A2_VS (A2_DK + 64 * KDP_ * 2)        // 32768
#define A2_PS 0                              // alias over Qs+Ks
#define A2_MS (A2_VS + TP_ * VP_ * 2)        // 44288
#define A2_MI (A2_MS + TP_ * 4)              // 44608
#define A2_CR (A2_MI + TP_ * 4)              // 44928
#define A2_SMEM (A2_CR + 128 * CRP_ * 4)     // 54144

__global__ __launch_bounds__(256) void attn2_k(
    const __half* __restrict__ q, const __half* __restrict__ kk,
    const __half* __restrict__ dksel, const __half* __restrict__ v2,
    const int* __restrict__ tokmask, const int* __restrict__ maskidx,
    float* __restrict__ posp, __half* __restrict__ ctx)
{
    extern __shared__ char dsm[];
    __half* Qs = (__half*)(dsm + A2_QS);
    __half* Ks = (__half*)(dsm + A2_KS);
    __half* Dk = (__half*)(dsm + A2_DK);
    __half* Vs = (__half*)(dsm + A2_VS);
    __half* Ph = (__half*)(dsm + A2_PS);
    float*  Ms = (float*)(dsm + A2_MS);
    int*    Mi = (int*)(dsm + A2_MI);
    float*  Crs = (float*)(dsm + A2_CR);

    const int b = blockIdx.z, h = blockIdx.y;
    const int tid = threadIdx.x;
    const int wid = tid >> 5, lane = tid & 31;
    const int bm0 = blockIdx.x * 128;

#pragma unroll
    for (int i = 0; i < 4; i++) {
        int f = tid + i * 256;
        int row = f >> 3, c8 = (f & 7) * 8;
        uint4 v = *(const uint4*)(q + ((size_t)(b * S_) + bm0 + row) * HD_ + h * D_ + c8);
        *(uint4*)&Qs[row * QP_ + c8] = v;
    }
    for (int f = tid; f < 64 * KP2_ / 2; f += 256) ((uint32_t*)Ks)[f] = 0;
    for (int f = tid; f < 64 * KDP_ / 2; f += 256) ((uint32_t*)Dk)[f] = 0;
    for (int f = tid; f < TP_ * VP_ / 2; f += 256) ((uint32_t*)Vs)[f] = 0;
    if (tid < TP_) {
        Ms[tid] = (tid < T_) ? (float)tokmask[b * T_ + tid] : 0.f;
        Mi[tid] = maskidx[b * TP_ + tid];
    }
    __syncthreads();
    for (int f = tid; f < T_ * 16; f += 256) {
        int t = f >> 4, d4 = (f & 15) * 4;
        uint2 u = *(const uint2*)(kk + ((size_t)(b * T_) + t) * HD_ + h * D_ + d4);
        const __half* hp = (const __half*)&u;
        Ks[(d4 + 0) * KP2_ + t] = hp[0];
        Ks[(d4 + 1) * KP2_ + t] = hp[1];
        Ks[(d4 + 2) * KP2_ + t] = hp[2];
        Ks[(d4 + 3) * KP2_ + t] = hp[3];
    }
    for (int f = tid; f < T_ * 8; f += 256) {
        int t = f >> 3, d8 = (f & 7) * 8;
        *(uint4*)&Vs[t * VP_ + d8] =
            *(const uint4*)(v2 + ((size_t)(b * T_) + t) * HD_ + h * D_ + d8);
    }
    {
        int f = tid;
        int j = f >> 4, d4 = (f & 15) * 4;
        uint2 u = *(const uint2*)(dksel + ((size_t)(b * 16 + j)) * HD_ + h * D_ + d4);
        const __half* hp = (const __half*)&u;
        Dk[(d4 + 0) * KDP_ + j] = hp[0];
        Dk[(d4 + 1) * KDP_ + j] = hp[1];
        Dk[(d4 + 2) * KDP_ + j] = hp[2];
        Dk[(d4 + 3) * KDP_ + j] = hp[3];
    }
    __syncthreads();

    const int ltile = lane >> 3, lrit = lane & 7;
    const int a_m  = wid * 16 + (ltile & 1) * 8 + lrit;
    const int a_kc = (ltile >> 1) * 8;
    const int b_k  = (ltile & 1) * 8 + lrit;
    const int b_n  = (ltile >> 1) * 8;
    const int r0   = wid * 16 + (lane >> 2);

    float acc[10][4];
    float accc[2][4];
#pragma unroll
    for (int nt = 0; nt < 10; nt++)
#pragma unroll
        for (int r = 0; r < 4; r++) acc[nt][r] = 0.f;
#pragma unroll
    for (int nt = 0; nt < 2; nt++)
#pragma unroll
        for (int r = 0; r < 4; r++) accc[nt][r] = 0.f;

#pragma unroll
    for (int kkk = 0; kkk < 64; kkk += 16) {
        uint32_t af[4], bf[10][2];
        ldmx4(af, &Qs[a_m * QP_ + kkk + a_kc]);
#pragma unroll
        for (int p = 0; p < 5; p++) {
            uint32_t br[4];
            ldmx4t(br, &Ks[(kkk + b_k) * KP2_ + b_n + p * 16]);
            bf[2 * p][0]     = br[0];
            bf[2 * p][1]     = br[1];
            bf[2 * p + 1][0] = br[2];
            bf[2 * p + 1][1] = br[3];
        }
#pragma unroll
        for (int nt = 0; nt < 10; nt++)
            mma_f16(acc[nt], af, bf[nt]);
        {
            uint32_t br[4];
            ldmx4t(br, &Dk[(kkk + b_k) * KDP_ + b_n]);
            uint32_t c0[2] = {br[0], br[1]};
            uint32_t c1[2] = {br[2], br[3]};
            mma_f16(accc[0], af, c0);
            mma_f16(accc[1], af, c1);
        }
    }

#pragma unroll
    for (int nt = 0; nt < 2; nt++) {
        int ccol = nt * 8 + 2 * (lane & 3);
        Crs[r0 * CRP_ + ccol]           = accc[nt][0];
        Crs[r0 * CRP_ + ccol + 1]       = accc[nt][1];
        Crs[(r0 + 8) * CRP_ + ccol]     = accc[nt][2];
        Crs[(r0 + 8) * CRP_ + ccol + 1] = accc[nt][3];
    }
    __syncwarp();

    float rsA_a = 0.f, rsA_b = 0.f, msA_a = 0.f, msA_b = 0.f;
    float rs2_a = 0.f, rs2_b = 0.f;
#pragma unroll
    for (int nt = 0; nt < 10; nt++) {
        int col = nt * 8 + 2 * (lane & 3);
        float m0 = Ms[col], m1 = Ms[col + 1];
        int j0 = Mi[col], j1 = Mi[col + 1];
        float l0 = acc[nt][0], l1 = acc[nt][1], l2 = acc[nt][2], l3 = acc[nt][3];
        float e0 = (col     < T_) ? __expf(l0 * SCALE_) : 0.f;
        float e1 = (col + 1 < T_) ? __expf(l1 * SCALE_) : 0.f;
        float e2 = (col     < T_) ? __expf(l2 * SCALE_) : 0.f;
        float e3 = (col + 1 < T_) ? __expf(l3 * SCALE_) : 0.f;
        rsA_a += e0 + e1; rsA_b += e2 + e3;
        msA_a += e0 * m0 + e1 * m1;
        msA_b += e2 * m0 + e3 * m1;
        float f0 = (j0 >= 0) ? __expf((l0 + Crs[r0 * CRP_ + j0]) * SCALE_) : e0;
        float f1 = (j1 >= 0) ? __expf((l1 + Crs[r0 * CRP_ + j1]) * SCALE_) : e1;
        float f2 = (j0 >= 0) ? __expf((l2 + Crs[(r0 + 8) * CRP_ + j0]) * SCALE_) : e2;
        float f3 = (j1 >= 0) ? __expf((l3 + Crs[(r0 + 8) * CRP_ + j1]) * SCALE_) : e3;
        rs2_a += f0 + f1; rs2_b += f2 + f3;
        acc[nt][0] = f0; acc[nt][1] = f1; acc[nt][2] = f2; acc[nt][3] = f3;
    }
    rsA_a += __shfl_xor_sync(0xffffffffu, rsA_a, 1);
    rsA_a += __shfl_xor_sync(0xffffffffu, rsA_a, 2);
    rsA_b += __shfl_xor_sync(0xffffffffu, rsA_b, 1);
    rsA_b += __shfl_xor_sync(0xffffffffu, rsA_b, 2);
    msA_a += __shfl_xor_sync(0xffffffffu, msA_a, 1);
    msA_a += __shfl_xor_sync(0xffffffffu, msA_a, 2);
    msA_b += __shfl_xor_sync(0xffffffffu, msA_b, 1);
    msA_b += __shfl_xor_sync(0xffffffffu, msA_b, 2);
    rs2_a += __shfl_xor_sync(0xffffffffu, rs2_a, 1);
    rs2_a += __shfl_xor_sync(0xffffffffu, rs2_a, 2);
    rs2_b += __shfl_xor_sync(0xffffffffu, rs2_b, 1);
    rs2_b += __shfl_xor_sync(0xffffffffu, rs2_b, 2);

    if ((lane & 3) == 0) {
        const size_t pb2 = (size_t)(b * H_ + h) * S_ + bm0;
        posp[pb2 + r0]     = msA_a / rsA_a;
        posp[pb2 + r0 + 8] = msA_b / rsA_b;
    }

    __syncthreads();   // Qs/Ks dead before Ph alias write

    float inv_a = 1.f / rs2_a;
    float inv_b = 1.f / rs2_b;
#pragma unroll
    for (int nt = 0; nt < 10; nt++) {
        int col = nt * 8 + 2 * (lane & 3);
        *(uint32_t*)&Ph[r0 * PP_ + col] =
            pack_h2(acc[nt][0] * inv_a, acc[nt][1] * inv_a);
        *(uint32_t*)&Ph[(r0 + 8) * PP_ + col] =
            pack_h2(acc[nt][2] * inv_b, acc[nt][3] * inv_b);
    }
    __syncthreads();

    float acc2[8][4];
#pragma unroll
    for (int nt = 0; nt < 8; nt++)
#pragma unroll
        for (int r = 0; r < 4; r++) acc2[nt][r] = 0.f;

#pragma unroll
    for (int kkk = 0; kkk < TP_; kkk += 16) {
        uint32_t af[4], bf[8][2];
        ldmx4(af, &Ph[a_m * PP_ + kkk + a_kc]);
#pragma unroll
        for (int p = 0; p < 4; p++) {
            uint32_t br[4];
            ldmx4t(br, &Vs[(kkk + b_k) * VP_ + b_n + p * 16]);
            bf[2 * p][0]     = br[0];
            bf[2 * p][1]     = br[1];
            bf[2 * p + 1][0] = br[2];
            bf[2 * p + 1][1] = br[3];
        }
#pragma unroll
        for (int nt = 0; nt < 8; nt++)
            mma_f16(acc2[nt], af, bf[nt]);
    }

#pragma unroll
    for (int nt = 0; nt < 8; nt++) {
        int col = nt * 8 + 2 * (lane & 3);
        *(uint32_t*)(ctx + ((size_t)(b * S_) + bm0 + r0) * HD_ + h * D_ + col) =
            pack_h2(acc2[nt][0], acc2[nt][1]);
        *(uint32_t*)(ctx + ((size_t)(b * S_) + bm0 + r0 + 8) * HD_ + h * D_ + col) =
            pack_h2(acc2[nt][2], acc2[nt][3]);
    }
}

// ---------------- fused batch-sum + patch injection (2 groups/thread) ----------------
#define NG8_ (S_ * HD_ / 8)
__global__ __launch_bounds__(256) void inject_fused_k(
    __half* __restrict__ ctx, const int* __restrict__ posmask)
{
    const int g = blockIdx.x * 256 + threadIdx.x;
    if (g >= NG8_ / 2) return;
#pragma unroll
    for (int half = 0; half < 2; half++) {
        const int i8 = g + half * (NG8_ / 2);
        const size_t base = (size_t)i8 * 8;
        const int s = (int)(base / HD_);

        float v[B_][8];
        float sum[8] = {0.f, 0.f, 0.f, 0.f, 0.f, 0.f, 0.f, 0.f};
#pragma unroll
        for (int b = 0; b < B_; b++) {
            uint4 u = *(const uint4*)(ctx + (size_t)b * S_ * HD_ + base);
            float2 f0 = __half22float2(*(__half2*)&u.x);
            float2 f1 = __half22float2(*(__half2*)&u.y);
            float2 f2 = __half22float2(*(__half2*)&u.z);
            float2 f3 = __half22float2(*(__half2*)&u.w);
            v[b][0] = f0.x; v[b][1] = f0.y; v[b][2] = f1.x; v[b][3] = f1.y;
            v[b][4] = f2.x; v[b][5] = f2.y; v[b][6] = f3.x; v[b][7] = f3.y;
#pragma unroll
            for (int j = 0; j < 8; j++) sum[j] += v[b][j];
        }
        const float c7 = 1.f / (float)(B_ - 1);
#pragma unroll
        for (int b = 0; b < B_; b++) {
            if (posmask[b * S_ + s]) {
                float o[8];
#pragma unroll
                for (int j = 0; j < 8; j++)
                    o[j] = v[b][j] + WINJ_ * ((sum[j] - v[b][j]) * c7 - v[b][j]);
                uint4 u;
                u.x = pack_h2(o[0], o[1]);
                u.y = pack_h2(o[2], o[3]);
                u.z = pack_h2(o[4], o[5]);
                u.w = pack_h2(o[6], o[7]);
                *(uint4*)(ctx + (size_t)b * S_ * HD_ + base) = u;
            }
        }
    }
}

// ---------------- launch ----------------
extern "C" void kernel_launch(void* const* d_in, const int* in_sizes, int n_in,
                              void* d_out, int out_size)
{
    (void)in_sizes; (void)n_in; (void)out_size;
    const float* X  = (const float*)d_in[0];
    const float* E  = (const float*)d_in[1];
    const float* Wq = (const float*)d_in[2];
    const float* Wk = (const float*)d_in[3];
    const float* Wv = (const float*)d_in[4];
    const float* Wo = (const float*)d_in[5];
    const float* bo = (const float*)d_in[6];
    float* out = (float*)d_out;

    __half *x16, *e16, *wq16, *wk16, *wv16, *wo16, *q, *k16, *v16, *v216, *dksel, *ctx;
    float *posp, *tokpart, *posscores;
    int *tokmask, *posmask, *tokidx, *maskidx;
    cudaGetSymbolAddress((void**)&x16,      g_x16);
    cudaGetSymbolAddress((void**)&e16,      g_e16);
    cudaGetSymbolAddress((void**)&wq16,     g_wq16);
    cudaGetSymbolAddress((void**)&wk16,     g_wk16);
    cudaGetSymbolAddress((void**)&wv16,     g_wv16);
    cudaGetSymbolAddress((void**)&wo16,     g_wo16);
    cudaGetSymbolAddress((void**)&q,        g_q);
    cudaGetSymbolAddress((void**)&k16,      g_k16);
    cudaGetSymbolAddress((void**)&v16,      g_v16);
    cudaGetSymbolAddress((void**)&v216,     g_v216);
    cudaGetSymbolAddress((void**)&dksel,    g_dksel);
    cudaGetSymbolAddress((void**)&tokidx,   g_tokidx);
    cudaGetSymbolAddress((void**)&maskidx,  g_maskidx);
    cudaGetSymbolAddress((void**)&posp,     g_posp);
    cudaGetSymbolAddress((void**)&tokpart,  g_tokpart);
    cudaGetSymbolAddress((void**)&tokmask,  g_tokmask);
    cudaGetSymbolAddress((void**)&posscores,g_posscores);
    cudaGetSymbolAddress((void**)&posmask,  g_posmask);
    cudaGetSymbolAddress((void**)&ctx,      g_ctx);

    cudaFuncSetAttribute(attn2_k, cudaFuncAttributeMaxDynamicSharedMemorySize, A2_SMEM);
    cudaFuncSetAttribute(hgemm16_k<1, 0>, cudaFuncAttributeMaxDynamicSharedMemorySize, GSM_TOTAL);
    cudaFuncSetAttribute(hgemm16_k<0, 1>, cudaFuncAttributeMaxDynamicSharedMemorySize, GSM_TOTAL);

    static cudaStream_t s2 = nullptr, s3 = nullptr;
    static cudaEvent_t evA = nullptr, evB = nullptr, evW = nullptr, evC2 = nullptr;
    static cudaEvent_t evTok = nullptr, evDk = nullptr, evQ1 = nullptr, evA1 = nullptr;
    if (s2 == nullptr) {
        cudaStreamCreateWithFlags(&s2, cudaStreamNonBlocking);
        cudaStreamCreateWithFlags(&s3, cudaStreamNonBlocking);
        cudaEventCreateWithFlags(&evA, cudaEventDisableTiming);
        cudaEventCreateWithFlags(&evB, cudaEventDisableTiming);
        cudaEventCreateWithFlags(&evW, cudaEventDisableTiming);
        cudaEventCreateWithFlags(&evC2, cudaEventDisableTiming);
        cudaEventCreateWithFlags(&evTok, cudaEventDisableTiming);
        cudaEventCreateWithFlags(&evDk, cudaEventDisableTiming);
        cudaEventCreateWithFlags(&evQ1, cudaEventDisableTiming);
        cudaEventCreateWithFlags(&evA1, cudaEventDisableTiming);
    }

    const int MH = B_ * S_ / 2;            // rows for batches 0..3
    const int XH4 = MH * C_ / 4;

    // fork A: side stream s2 — Wq weight cvt first, then E/W cvts + K/V projections
    cudaEventRecord(evA, 0);
    cudaStreamWaitEvent(s2, evA, 0);
    cudaStreamWaitEvent(s3, evA, 0);
    cvt16_k<<<(C_ * HD_ / 4 + 255) / 256, 256, 0, s2>>>(Wq, wq16, C_ * HD_ / 4);
    cudaEventRecord(evW, s2);
    cvt16_k<<<(B_ * T_ * CE_ / 4 + 255) / 256, 256, 0, s2>>>(E, e16, B_ * T_ * CE_ / 4);
    cvt16_k<<<(CE_ * HD_ / 4 + 255) / 256, 256, 0, s2>>>(Wk, wk16, CE_ * HD_ / 4);
    cvt16_k<<<(CE_ * HD_ / 4 + 255) / 256, 256, 0, s2>>>(Wv, wv16, CE_ * HD_ / 4);
    cvt16_k<<<(HD_ * C_ / 4 + 255) / 256, 256, 0, s2>>>(Wo, wo16, HD_ * C_ / 4);
    hgemm16_k<1, 0><<<dim3(HD_ / 128, (B_ * T_ + 127) / 128), 256, GSM_TOTAL, s2>>>(
        e16, wk16, k16, B_ * T_, HD_, CE_, nullptr, nullptr);
    hgemm16_k<1, 0><<<dim3(HD_ / 128, (B_ * T_ + 127) / 128), 256, GSM_TOTAL, s2>>>(
        e16, wv16, v16, B_ * T_, HD_, CE_, nullptr, nullptr);
    cudaEventRecord(evB, s2);

    // fork B: s3 converts X half-2 concurrent with main's half-1 cvt + Wq half-1
    cvt16_k<<<(XH4 + 255) / 256, 256, 0, s3>>>(X + (size_t)MH * C_, x16 + (size_t)MH * C_, XH4);
    cudaEventRecord(evC2, s3);

    // main: X half-1 cvt, Wq half-1
    cvt16_k<<<(XH4 + 255) / 256, 256>>>(X, x16, XH4);
    cudaStreamWaitEvent(0, evW, 0);
    hgemm16_k<1, 0><<<dim3(HD_ / 128, MH / 128), 256, GSM_TOTAL>>>(
        x16, wq16, q, MH, HD_, C_, nullptr, nullptr);
    cudaEventRecord(evQ1, 0);

    // s3: attn1 for batches 0..3 concurrent with Wq half-2 (needs q half-1 + k16)
    cudaStreamWaitEvent(s3, evQ1, 0);
    cudaStreamWaitEvent(s3, evB, 0);
    attn1_k<<<dim3(SCHUNK_, H_, 4), 256, 0, s3>>>(q, k16, tokpart, 0);
    cudaEventRecord(evA1, s3);

    // main: Wq half-2
    cudaStreamWaitEvent(0, evC2, 0);
    hgemm16_k<1, 0><<<dim3(HD_ / 128, MH / 128), 256, GSM_TOTAL>>>(
        x16 + (size_t)MH * C_, wq16, q + (size_t)MH * HD_, MH, HD_, C_, nullptr, nullptr);
    cudaStreamWaitEvent(0, evB, 0);

    // main: attn1 for batches 4..7, join with s3's half
    attn1_k<<<dim3(SCHUNK_, H_, 4), 256>>>(q, k16, tokpart, 4);
    cudaStreamWaitEvent(0, evA1, 0);
    tok_topk_k<<<B_, 128>>>(tokpart, tokmask, tokidx, maskidx);
    cudaEventRecord(evTok, 0);

    // dksel on s2 concurrent with vmix on main
    cudaStreamWaitEvent(s2, evTok, 0);
    dksel_k<<<(B_ * 16 * (HD_ / 4) + 255) / 256, 256, 0, s2>>>(k16, tokidx, dksel);
    cudaEventRecord(evDk, s2);
    vmix_k<<<(T_ * HD_ + 255) / 256, 256>>>(v16, tokmask, v216);
    cudaStreamWaitEvent(0, evDk, 0);

    // attn pass 2 -> pos partials + fp16 ctx
    attn2_k<<<dim3(SCHUNK_, H_, B_), 256, A2_SMEM>>>(q, k16, dksel, v216, tokmask, maskidx, posp, ctx);

    // pos mask
    pos_reduce_k<<<(B_ * S_ + 255) / 256, 256>>>(posp, posscores);
    pos_topk_k<<<dim3(S_ / 256, B_), 256>>>(posscores, posmask);

    // injection
    inject_fused_k<<<(NG8_ / 2 + 255) / 256, 256>>>(ctx, posmask);

    // output projection + bias + fp16 residual
    hgemm16_k<0, 1><<<dim3(HD_ / 128, (B_ * S_) / 128), 256, GSM_TOTAL>>>(
        ctx, wo16, out, B_ * S_, HD_, C_, bo, x16);
}